// round 8
// baseline (speedup 1.0000x reference)
#include <cuda_runtime.h>
#include <cuda_fp16.h>

#define M_NODES 100000
#define HID     256
#define NREL    6
#define EPR     100000
#define NEDGE   (NREL * EPR)        // 600000
#define NOUT    256
#define KTOT    1792                // 6*256 + 256
#define NGRAPH  128

#define BM 128
#define FSMEM (4*16384 + 2*16384)   // A: 4 subtiles 128x64 fp16, B: 2 stages = 98304

#define NBIN   (M_NODES * NREL)     // 600000 (tgt,rel) bins
#define SCAN_BLK 1024
#define NSCAN2 ((NBIN + SCAN_BLK - 1) / SCAN_BLK)    // 586

// ---------------- scratch (device globals; no allocation allowed) ----------------
__device__ __half  g_hA16[(size_t)M_NODES * HID];
__device__ __half  g_hB16[(size_t)M_NODES * HID];
__device__ __half  g_Wt2[NOUT * KTOT];             // [n][k]
__device__ float   g_invdeg[M_NODES];
__device__ int     g_deg2[NBIN];
__device__ int     g_off2[NBIN + 1];
__device__ int     g_bsum[NSCAN2];
__device__ int     g_bbase[NSCAN2];
__device__ int     g_cur2[NBIN];
__device__ int     g_eidx[NEDGE];                  // src, grouped by (tgt,rel)
__device__ float   g_pooled[NGRAPH * HID];
__device__ int     g_counts[NGRAPH];

// ---------------- PTX helpers (baseline ISA; nothing 'a'-gated) ----------------
__device__ __forceinline__ unsigned su32(const void* p) {
    return (unsigned)__cvta_generic_to_shared(p);
}
__device__ __forceinline__ void cp16(void* sm, const void* gm) {
    asm volatile("cp.async.cg.shared.global [%0], [%1], 16;" :: "r"(su32(sm)), "l"(gm));
}
#define CP_COMMIT() asm volatile("cp.async.commit_group;" ::: "memory")
#define CP_WAIT(n)  asm volatile("cp.async.wait_group %0;" :: "n"(n) : "memory")

__device__ __forceinline__ void ldsm4(unsigned* r, unsigned addr) {
    asm volatile("ldmatrix.sync.aligned.m8n8.x4.shared.b16 {%0,%1,%2,%3}, [%4];"
                 : "=r"(r[0]), "=r"(r[1]), "=r"(r[2]), "=r"(r[3]) : "r"(addr));
}
__device__ __forceinline__ void mma16816(float* c, const unsigned* a, unsigned b0, unsigned b1) {
    asm volatile("mma.sync.aligned.m16n8k16.row.col.f32.f16.f16.f32 "
                 "{%0,%1,%2,%3}, {%4,%5,%6,%7}, {%8,%9}, {%0,%1,%2,%3};"
                 : "+f"(c[0]), "+f"(c[1]), "+f"(c[2]), "+f"(c[3])
                 : "r"(a[0]), "r"(a[1]), "r"(a[2]), "r"(a[3]), "r"(b0), "r"(b1));
}
__device__ __forceinline__ unsigned swz(unsigned off) {
    return off ^ ((off >> 3) & 0x70);
}

// ---------------- small kernels ----------------
__global__ void embed_kernel(const int* __restrict__ x_type, const int* __restrict__ x_sub,
                             const float* __restrict__ temb, const float* __restrict__ semb,
                             __half* __restrict__ h0)
{
    int gid = blockIdx.x * 256 + threadIdx.x;
    if (gid < M_NODES * HID) {
        int n = gid >> 8, c = gid & 255;
        float v = (c < 128) ? temb[x_type[n] * 128 + c] : semb[x_sub[n] * 128 + (c - 128)];
        h0[gid] = __float2half_rn(v);
    }
}

__global__ void degree2_kernel(const int* __restrict__ edges, int* __restrict__ deg2)
{
    int i = blockIdx.x * 256 + threadIdx.x;
    if (i < NEDGE) {
        int r = i / EPR, e = i % EPR;
        int tgt = edges[r * 2 * EPR + EPR + e];
        atomicAdd(&deg2[tgt * NREL + r], 1);
    }
}

// ---- generic 3-phase exclusive scan ----
__global__ void blocksum_kernel(const int* __restrict__ v_in, int* __restrict__ bsum, int n)
{
    __shared__ int ws[32];
    int i = blockIdx.x * SCAN_BLK + threadIdx.x;
    int v = (i < n) ? v_in[i] : 0;
#pragma unroll
    for (int o = 16; o; o >>= 1) v += __shfl_down_sync(0xffffffff, v, o);
    if ((threadIdx.x & 31) == 0) ws[threadIdx.x >> 5] = v;
    __syncthreads();
    if (threadIdx.x < 32) {
        int s = ws[threadIdx.x];
#pragma unroll
        for (int o = 16; o; o >>= 1) s += __shfl_down_sync(0xffffffff, s, o);
        if (threadIdx.x == 0) bsum[blockIdx.x] = s;
    }
}

__global__ void bscan_kernel(const int* __restrict__ bsum, int* __restrict__ bbase, int n)
{
    // n <= 1024, single block of 1024
    __shared__ int wsum[32];
    __shared__ int wbase[32];
    int tid = threadIdx.x, lane = tid & 31, wid = tid >> 5;
    int v = (tid < n) ? bsum[tid] : 0;
    int x = v;
#pragma unroll
    for (int o = 1; o < 32; o <<= 1) {
        int t = __shfl_up_sync(0xffffffff, x, o);
        if (lane >= o) x += t;
    }
    if (lane == 31) wsum[wid] = x;
    __syncthreads();
    if (wid == 0) {
        int s = wsum[lane];
        int y = s;
#pragma unroll
        for (int o = 1; o < 32; o <<= 1) {
            int t = __shfl_up_sync(0xffffffff, y, o);
            if (lane >= o) y += t;
        }
        wbase[lane] = y - s;
    }
    __syncthreads();
    if (tid < n) bbase[tid] = wbase[wid] + x - v;
}

__global__ void offsets_kernel(const int* __restrict__ v_in, const int* __restrict__ bbase,
                               int* __restrict__ off, int n, int total)
{
    __shared__ int wsum[32];
    __shared__ int wbase[32];
    int i = blockIdx.x * SCAN_BLK + threadIdx.x;
    int lane = threadIdx.x & 31, wid = threadIdx.x >> 5;
    int v = (i < n) ? v_in[i] : 0;
    int x = v;
#pragma unroll
    for (int o = 1; o < 32; o <<= 1) {
        int t = __shfl_up_sync(0xffffffff, x, o);
        if (lane >= o) x += t;
    }
    if (lane == 31) wsum[wid] = x;
    __syncthreads();
    if (wid == 0) {
        int s = wsum[lane];
        int y = s;
#pragma unroll
        for (int o = 1; o < 32; o <<= 1) {
            int t = __shfl_up_sync(0xffffffff, y, o);
            if (lane >= o) y += t;
        }
        wbase[lane] = y - s;
    }
    __syncthreads();
    if (i < n) off[i] = bbase[blockIdx.x] + wbase[wid] + x - v;
    if (i == 0) off[n] = total;
}

__global__ void invdeg2_kernel(const int* __restrict__ off2, float* __restrict__ invd)
{
    int i = blockIdx.x * 256 + threadIdx.x;
    if (i < M_NODES) {
        int d = off2[(i + 1) * NREL] - off2[i * NREL];
        invd[i] = 1.0f / (float)(d > 1 ? d : 1);
    }
}

__global__ void fill2_kernel(const int* __restrict__ edges, const int* __restrict__ off2,
                             int* __restrict__ cur2, int* __restrict__ eidx)
{
    int i = blockIdx.x * 256 + threadIdx.x;
    if (i < NEDGE) {
        int r = i / EPR, e = i % EPR;
        int src = edges[r * 2 * EPR + e];
        int tgt = edges[r * 2 * EPR + EPR + e];
        int bin = tgt * NREL + r;
        int slot = off2[bin] + atomicAdd(&cur2[bin], 1);
        eidx[slot] = src;
    }
}

// Wt2[n][k]: k<1536 -> Wrel[k*256+n] (k=r*256+h), else Wself[(k-1536)*256+n]
__global__ void convW_kernel(const float* __restrict__ Wrel, const float* __restrict__ Wself,
                             __half* __restrict__ Wt2)
{
    int idx = blockIdx.x * 256 + threadIdx.x;
    if (idx < NOUT * KTOT) {
        int n = idx / KTOT, k = idx - n * KTOT;
        float v = (k < 1536) ? Wrel[(size_t)k * 256 + n] : Wself[(size_t)(k - 1536) * 256 + n];
        Wt2[idx] = __float2half_rn(v);
    }
}

// ---------------- fused layer: gather(Agg)+GEMM+bias+relu in one kernel ----------------
// out[m][n] = relu( sum_r (invd[m]*sum_{e in (m,r)} h[src]) @ Wrel_r + h[m] @ Wself + b )
// grid (2, 782), 256 threads. A built in smem per rel (4 subtiles of 128x64), B via cp.async.
__global__ __launch_bounds__(256, 2)
void fused_layer(const __half* __restrict__ hin, const __half* __restrict__ Wt2,
                 const int* __restrict__ off2, const int* __restrict__ eidx,
                 const float* __restrict__ invd, const float* __restrict__ bias,
                 __half* __restrict__ hout)
{
    extern __shared__ unsigned char smraw[];
    const int tid  = threadIdx.x;
    const int lane = tid & 31;
    const int wid  = tid >> 5;
    const int wm   = wid & 3;
    const int wn   = wid >> 2;
    const int m0   = blockIdx.y * BM;
    const int n0   = blockIdx.x * 128;

    float acc[2][8][4];
#pragma unroll
    for (int mi = 0; mi < 2; mi++)
#pragma unroll
        for (int ni = 0; ni < 8; ni++)
#pragma unroll
            for (int j = 0; j < 4; j++) acc[mi][ni][j] = 0.0f;

    const int brow = tid >> 3;      // B loader: 0..31
    const int bseg = tid & 7;
    const int grow = tid >> 4;      // gather: 16 threads/row, 16 rows/pass
    const int gt   = tid & 15;      // 16 cols (32B) per thread

    auto issueB = [&](int kglob, int st) {
        unsigned char* Bs = smraw + 65536 + st * 16384;
#pragma unroll
        for (int p = 0; p < 4; p++) {
            int row = brow + p * 32;
            unsigned so = swz((unsigned)(row * 128 + bseg * 16));
            cp16(Bs + so, Wt2 + (size_t)(n0 + row) * KTOT + kglob * 64 + bseg * 8);
        }
        CP_COMMIT();
    };

    auto computeSub = [&](int asub, int st) {
        unsigned ab = su32(smraw + asub * 16384);
        unsigned bb = su32(smraw + 65536 + st * 16384);
#pragma unroll
        for (int ks = 0; ks < 4; ++ks) {
            unsigned a[2][4], b[4][4];
#pragma unroll
            for (int mi = 0; mi < 2; mi++) {
                int row = wm * 32 + mi * 16 + (lane & 15);
                unsigned off = (unsigned)(row * 128 + ks * 32 + (lane >> 4) * 16);
                ldsm4(a[mi], ab + swz(off));
            }
#pragma unroll
            for (int nj = 0; nj < 4; nj++) {
                int q = lane >> 3, r2 = lane & 7;
                int nrow = wn * 64 + nj * 16 + (q >> 1) * 8 + r2;
                unsigned off = (unsigned)(nrow * 128 + ks * 32 + (q & 1) * 16);
                ldsm4(b[nj], bb + swz(off));
            }
#pragma unroll
            for (int mi = 0; mi < 2; mi++)
#pragma unroll
                for (int ni = 0; ni < 8; ni++)
                    mma16816(acc[mi][ni], a[mi], b[ni >> 1][(ni & 1) * 2], b[ni >> 1][(ni & 1) * 2 + 1]);
        }
    };

    for (int r = 0; r < 7; r++) {
        issueB(r * 4 + 0, 0);
        issueB(r * 4 + 1, 1);

        // ---- fill A subtiles (128 rows x 256 cols as 4x [128][64]) ----
        if (r < 6) {
#pragma unroll 1
            for (int p = 0; p < 8; p++) {
                int row = p * 16 + grow;
                int node = m0 + row;
                float a[16];
#pragma unroll
                for (int j = 0; j < 16; j++) a[j] = 0.0f;
                if (node < M_NODES) {
                    int bin = node * NREL + r;
                    int e = off2[bin], end = off2[bin + 1];
                    if (e < end) {
                        int src = __ldg(&eidx[e]);
                        while (e < end) {
                            int nsrc = (e + 1 < end) ? __ldg(&eidx[e + 1]) : 0;
                            const uint4* hp = (const uint4*)(hin + (size_t)src * HID + gt * 16);
                            uint4 u0 = __ldg(hp);
                            uint4 u1 = __ldg(hp + 1);
                            const __half2* x0 = (const __half2*)&u0;
                            const __half2* x1 = (const __half2*)&u1;
#pragma unroll
                            for (int k = 0; k < 4; k++) {
                                float2 f = __half22float2(x0[k]);
                                a[2 * k] += f.x; a[2 * k + 1] += f.y;
                            }
#pragma unroll
                            for (int k = 0; k < 4; k++) {
                                float2 f = __half22float2(x1[k]);
                                a[8 + 2 * k] += f.x; a[9 + 2 * k] += f.y;
                            }
                            src = nsrc;
                            e++;
                        }
                        float w = invd[node];
#pragma unroll
                        for (int j = 0; j < 16; j++) a[j] *= w;
                    }
                }
                uint4 o0, o1;
                __half2* ph0 = (__half2*)&o0;
                __half2* ph1 = (__half2*)&o1;
#pragma unroll
                for (int k = 0; k < 4; k++) {
                    ph0[k] = __floats2half2_rn(a[2 * k], a[2 * k + 1]);
                    ph1[k] = __floats2half2_rn(a[8 + 2 * k], a[9 + 2 * k]);
                }
                unsigned base = (unsigned)(gt >> 2) * 16384;
                unsigned off0 = (unsigned)(row * 128 + (gt & 3) * 32);
                *(uint4*)(smraw + base + swz(off0))      = o0;
                *(uint4*)(smraw + base + swz(off0 + 16)) = o1;
            }
        } else {
            // self chunk: copy hin tile
#pragma unroll 1
            for (int p = 0; p < 8; p++) {
                int row = p * 16 + grow;
                int node = m0 + row; if (node > M_NODES - 1) node = M_NODES - 1;
                const uint4* hp = (const uint4*)(hin + (size_t)node * HID + gt * 16);
                uint4 u0 = __ldg(hp);
                uint4 u1 = __ldg(hp + 1);
                unsigned base = (unsigned)(gt >> 2) * 16384;
                unsigned off0 = (unsigned)(row * 128 + (gt & 3) * 32);
                *(uint4*)(smraw + base + swz(off0))      = u0;
                *(uint4*)(smraw + base + swz(off0 + 16)) = u1;
            }
        }
        __syncthreads();

        // ---- 4 MMA sub-chunks with 2-stage B pipeline ----
        CP_WAIT(1); __syncthreads();
        computeSub(0, 0); __syncthreads();
        issueB(r * 4 + 2, 0);
        CP_WAIT(1); __syncthreads();
        computeSub(1, 1); __syncthreads();
        issueB(r * 4 + 3, 1);
        CP_WAIT(1); __syncthreads();
        computeSub(2, 0); __syncthreads();
        CP_WAIT(0); __syncthreads();
        computeSub(3, 1); __syncthreads();
    }

    // ---- epilogue: + bias, relu, fp16 store (row stride 256) ----
    const int cb = n0 + wn * 64 + (lane & 3) * 2;
    float bb0[8], bb1[8];
#pragma unroll
    for (int ni = 0; ni < 8; ni++) {
        bb0[ni] = __ldg(&bias[cb + ni * 8]);
        bb1[ni] = __ldg(&bias[cb + ni * 8 + 1]);
    }
#pragma unroll
    for (int mi = 0; mi < 2; mi++) {
        int r0 = m0 + wm * 32 + mi * 16 + (lane >> 2);
        int r1 = r0 + 8;
        if (r0 < M_NODES) {
            __half* dst = hout + (size_t)r0 * HID + cb;
#pragma unroll
            for (int ni = 0; ni < 8; ni++) {
                float v0 = fmaxf(acc[mi][ni][0] + bb0[ni], 0.f);
                float v1 = fmaxf(acc[mi][ni][1] + bb1[ni], 0.f);
                *(__half2*)(dst + ni * 8) = __floats2half2_rn(v0, v1);
            }
        }
        if (r1 < M_NODES) {
            __half* dst = hout + (size_t)r1 * HID + cb;
#pragma unroll
            for (int ni = 0; ni < 8; ni++) {
                float v0 = fmaxf(acc[mi][ni][2] + bb0[ni], 0.f);
                float v1 = fmaxf(acc[mi][ni][3] + bb1[ni], 0.f);
                *(__half2*)(dst + ni * 8) = __floats2half2_rn(v0, v1);
            }
        }
    }
}

// ---------------- pooling + MLP ----------------
__global__ void count_kernel(const int* __restrict__ bids, int* __restrict__ counts)
{
    int g = threadIdx.x;
    if (g >= NGRAPH) return;
    int lo = 0, hi = M_NODES;
    while (lo < hi) { int mid = (lo + hi) >> 1; if (bids[mid] < g) lo = mid + 1; else hi = mid; }
    int start = lo;
    lo = 0; hi = M_NODES;
    while (lo < hi) { int mid = (lo + hi) >> 1; if (bids[mid] <= g) lo = mid + 1; else hi = mid; }
    counts[g] = lo - start;
}

__global__ void pool_sum_kernel(const __half* __restrict__ h, const int* __restrict__ bids,
                                float* __restrict__ pooled)
{
    int c = threadIdx.x;
    int n_start = blockIdx.x * 256;
    int n_end = n_start + 256;
    if (n_end > M_NODES) n_end = M_NODES;
    if (n_start >= M_NODES) return;
    int cur = bids[n_start];
    float acc = 0.0f;
    for (int n = n_start; n < n_end; n++) {
        int g = bids[n];
        if (g != cur) { atomicAdd(&pooled[cur * HID + c], acc); acc = 0.0f; cur = g; }
        acc += __half2float(h[(size_t)n * HID + c]);
    }
    atomicAdd(&pooled[cur * HID + c], acc);
}

__global__ void mlp_kernel(const float* __restrict__ pooled, const int* __restrict__ counts,
                           const float* __restrict__ pW1, const float* __restrict__ pb1,
                           const float* __restrict__ pW2, const float* __restrict__ pb2,
                           float* __restrict__ out)
{
    __shared__ float p[HID];
    __shared__ float t[HID];
    int g = blockIdx.x, d = threadIdx.x;
    int cn = counts[g];
    float inv = 1.0f / (float)(cn > 1 ? cn : 1);
    p[d] = pooled[g * HID + d] * inv;
    __syncthreads();
    float a = pb1[d];
#pragma unroll 8
    for (int k = 0; k < HID; k++) a += p[k] * pW1[k * HID + d];
    t[d] = a > 0.f ? a : 0.f;
    __syncthreads();
    float o = pb2[d];
#pragma unroll 8
    for (int k = 0; k < HID; k++) o += t[k] * pW2[k * HID + d];
    out[g * HID + d] = o;
}

// ---------------------------------------------------------------
extern "C" void kernel_launch(void* const* d_in, const int* in_sizes, int n_in,
                              void* d_out, int out_size)
{
    const int*   x_type = (const int*)d_in[0];
    const int*   x_sub  = (const int*)d_in[1];
    const int*   edges  = (const int*)d_in[2];
    const int*   bids   = (const int*)d_in[3];
    const float* temb   = (const float*)d_in[5];
    const float* semb   = (const float*)d_in[6];
    const float* Wrel0  = (const float*)d_in[7];
    const float* Wself0 = (const float*)d_in[8];
    const float* b0     = (const float*)d_in[9];
    const float* Wrel1  = (const float*)d_in[10];
    const float* Wself1 = (const float*)d_in[11];
    const float* b1     = (const float*)d_in[12];
    const float* pW1    = (const float*)d_in[13];
    const float* pb1    = (const float*)d_in[14];
    const float* pW2    = (const float*)d_in[15];
    const float* pb2    = (const float*)d_in[16];
    float* out = (float*)d_out;

    void *phA, *phB, *pWt2, *pinv, *pdeg2, *poff2, *pbsum, *pbbase, *pcur2, *peidx, *ppooled, *pcnt;
    cudaGetSymbolAddress(&phA, g_hA16);
    cudaGetSymbolAddress(&phB, g_hB16);
    cudaGetSymbolAddress(&pWt2, g_Wt2);
    cudaGetSymbolAddress(&pinv, g_invdeg);
    cudaGetSymbolAddress(&pdeg2, g_deg2);
    cudaGetSymbolAddress(&poff2, g_off2);
    cudaGetSymbolAddress(&pbsum, g_bsum);
    cudaGetSymbolAddress(&pbbase, g_bbase);
    cudaGetSymbolAddress(&pcur2, g_cur2);
    cudaGetSymbolAddress(&peidx, g_eidx);
    cudaGetSymbolAddress(&ppooled, g_pooled);
    cudaGetSymbolAddress(&pcnt, g_counts);

    cudaFuncSetAttribute(fused_layer, cudaFuncAttributeMaxDynamicSharedMemorySize, FSMEM);

    cudaMemsetAsync(pdeg2, 0, NBIN * sizeof(int));
    cudaMemsetAsync(pcur2, 0, NBIN * sizeof(int));
    cudaMemsetAsync(ppooled, 0, NGRAPH * HID * sizeof(float));

    embed_kernel<<<(M_NODES * HID + 255) / 256, 256>>>(x_type, x_sub, temb, semb, (__half*)phA);

    // CSR by (tgt, rel)
    degree2_kernel<<<(NEDGE + 255) / 256, 256>>>(edges, (int*)pdeg2);
    blocksum_kernel<<<NSCAN2, SCAN_BLK>>>((const int*)pdeg2, (int*)pbsum, NBIN);
    bscan_kernel<<<1, 1024>>>((const int*)pbsum, (int*)pbbase, NSCAN2);
    offsets_kernel<<<NSCAN2, SCAN_BLK>>>((const int*)pdeg2, (const int*)pbbase, (int*)poff2, NBIN, NEDGE);
    invdeg2_kernel<<<(M_NODES + 255) / 256, 256>>>((const int*)poff2, (float*)pinv);
    fill2_kernel<<<(NEDGE + 255) / 256, 256>>>(edges, (const int*)poff2, (int*)pcur2, (int*)peidx);

    dim3 fgrid(2, (M_NODES + BM - 1) / BM);   // (2, 782)

    // ---- layer 0: hA -> hB ----
    convW_kernel<<<(NOUT * KTOT + 255) / 256, 256>>>(Wrel0, Wself0, (__half*)pWt2);
    fused_layer<<<fgrid, 256, FSMEM>>>((const __half*)phA, (const __half*)pWt2,
                                       (const int*)poff2, (const int*)peidx,
                                       (const float*)pinv, b0, (__half*)phB);

    // ---- layer 1: hB -> hA ----
    convW_kernel<<<(NOUT * KTOT + 255) / 256, 256>>>(Wrel1, Wself1, (__half*)pWt2);
    fused_layer<<<fgrid, 256, FSMEM>>>((const __half*)phB, (const __half*)pWt2,
                                       (const int*)poff2, (const int*)peidx,
                                       (const float*)pinv, b1, (__half*)phA);

    // ---- pool + MLP ----
    count_kernel<<<1, 128>>>(bids, (int*)pcnt);
    pool_sum_kernel<<<(M_NODES + 255) / 256, 256>>>((const __half*)phA, bids, (float*)ppooled);
    mlp_kernel<<<NGRAPH, 256>>>((const float*)ppooled, (const int*)pcnt, pW1, pb1, pW2, pb2, out);
}

// round 9
// speedup vs baseline: 1.2038x; 1.2038x over previous
#include <cuda_runtime.h>
#include <cuda_fp16.h>

#define M_NODES 100000
#define HID     256
#define NREL    6
#define EPR     100000
#define NEDGE   (NREL * EPR)        // 600000
#define NMSG    1792                // 6*256 rel msgs + 256 self
#define NGRAPH  128

#define BM 128
#define BN 128
#define BK 64
#define NCHUNK (HID / BK)           // 4
#define GSMEM  (2 * (BM + BN) * BK * 2)   // 65536 (2-stage)

#define SCAN_BLK 1024
#define NSCAN ((M_NODES + SCAN_BLK - 1) / SCAN_BLK)   // 98

// ---------------- scratch (device globals; no allocation allowed) ----------------
__device__ __half  g_hA16[(size_t)M_NODES * HID];
__device__ __half  g_hB16[(size_t)M_NODES * HID];
__device__ __half  g_msg[(size_t)M_NODES * NMSG];      // 358.4 MB
__device__ __half  g_Wt[NMSG * HID];
__device__ float   g_invdeg[M_NODES];
__device__ int     g_deg[M_NODES];
__device__ int     g_off[M_NODES + 1];
__device__ int     g_bsum[NSCAN];
__device__ int     g_bbase[NSCAN];
__device__ int     g_cursor[M_NODES];
__device__ int     g_eidx[NEDGE];                      // packed (src<<3)|r, grouped by tgt
__device__ float   g_pooled[NGRAPH * HID];
__device__ int     g_counts[NGRAPH];

// ---------------- PTX helpers (baseline ISA; nothing 'a'-gated) ----------------
__device__ __forceinline__ unsigned su32(const void* p) {
    return (unsigned)__cvta_generic_to_shared(p);
}
__device__ __forceinline__ void cp16(void* sm, const void* gm) {
    asm volatile("cp.async.cg.shared.global [%0], [%1], 16;" :: "r"(su32(sm)), "l"(gm));
}
#define CP_COMMIT() asm volatile("cp.async.commit_group;" ::: "memory")
#define CP_WAIT(n)  asm volatile("cp.async.wait_group %0;" :: "n"(n) : "memory")

__device__ __forceinline__ void ldsm4(unsigned* r, unsigned addr) {
    asm volatile("ldmatrix.sync.aligned.m8n8.x4.shared.b16 {%0,%1,%2,%3}, [%4];"
                 : "=r"(r[0]), "=r"(r[1]), "=r"(r[2]), "=r"(r[3]) : "r"(addr));
}
__device__ __forceinline__ void mma16816(float* c, const unsigned* a, unsigned b0, unsigned b1) {
    asm volatile("mma.sync.aligned.m16n8k16.row.col.f32.f16.f16.f32 "
                 "{%0,%1,%2,%3}, {%4,%5,%6,%7}, {%8,%9}, {%0,%1,%2,%3};"
                 : "+f"(c[0]), "+f"(c[1]), "+f"(c[2]), "+f"(c[3])
                 : "r"(a[0]), "r"(a[1]), "r"(a[2]), "r"(a[3]), "r"(b0), "r"(b1));
}
__device__ __forceinline__ unsigned swz(unsigned off) {
    return off ^ ((off >> 3) & 0x70);
}

// ---------------- small kernels ----------------
__global__ void embed_kernel(const int* __restrict__ x_type, const int* __restrict__ x_sub,
                             const float* __restrict__ temb, const float* __restrict__ semb,
                             __half* __restrict__ h0)
{
    int gid = blockIdx.x * 256 + threadIdx.x;
    if (gid < M_NODES * HID) {
        int n = gid >> 8, c = gid & 255;
        float v = (c < 128) ? temb[x_type[n] * 128 + c] : semb[x_sub[n] * 128 + (c - 128)];
        h0[gid] = __float2half_rn(v);
    }
}

__global__ void degree_kernel(const int* __restrict__ edges, int* __restrict__ deg)
{
    int i = blockIdx.x * 256 + threadIdx.x;
    if (i < NEDGE) {
        int r = i / EPR, e = i % EPR;
        atomicAdd(&deg[edges[r * 2 * EPR + EPR + e]], 1);
    }
}

__global__ void invdeg_kernel(const int* __restrict__ deg, float* __restrict__ invd)
{
    int i = blockIdx.x * 256 + threadIdx.x;
    if (i < M_NODES) {
        int d = deg[i];
        invd[i] = 1.0f / (float)(d > 1 ? d : 1);
    }
}

// ---- parallel 3-phase exclusive scan of deg -> off ----
__global__ void blocksum_kernel(const int* __restrict__ deg, int* __restrict__ bsum)
{
    __shared__ int ws[32];
    int i = blockIdx.x * SCAN_BLK + threadIdx.x;
    int v = (i < M_NODES) ? deg[i] : 0;
#pragma unroll
    for (int o = 16; o; o >>= 1) v += __shfl_down_sync(0xffffffff, v, o);
    if ((threadIdx.x & 31) == 0) ws[threadIdx.x >> 5] = v;
    __syncthreads();
    if (threadIdx.x < 32) {
        int s = ws[threadIdx.x];
#pragma unroll
        for (int o = 16; o; o >>= 1) s += __shfl_down_sync(0xffffffff, s, o);
        if (threadIdx.x == 0) bsum[blockIdx.x] = s;
    }
}

__global__ void bscan_kernel(const int* __restrict__ bsum, int* __restrict__ bbase)
{
    __shared__ int wsum[4];
    __shared__ int wbase[4];
    int tid = threadIdx.x, lane = tid & 31, wid = tid >> 5;
    int v = (tid < NSCAN) ? bsum[tid] : 0;
    int x = v;
#pragma unroll
    for (int o = 1; o < 32; o <<= 1) {
        int t = __shfl_up_sync(0xffffffff, x, o);
        if (lane >= o) x += t;
    }
    if (lane == 31) wsum[wid] = x;
    __syncthreads();
    if (tid == 0) {
        int a = 0;
#pragma unroll
        for (int w = 0; w < 4; w++) { int t = wsum[w]; wbase[w] = a; a += t; }
    }
    __syncthreads();
    if (tid < NSCAN) bbase[tid] = wbase[wid] + x - v;   // exclusive
}

__global__ void offsets_kernel(const int* __restrict__ deg, const int* __restrict__ bbase,
                               int* __restrict__ off)
{
    __shared__ int wsum[32];
    __shared__ int wbase[32];
    int i = blockIdx.x * SCAN_BLK + threadIdx.x;
    int lane = threadIdx.x & 31, wid = threadIdx.x >> 5;
    int v = (i < M_NODES) ? deg[i] : 0;
    int x = v;
#pragma unroll
    for (int o = 1; o < 32; o <<= 1) {
        int t = __shfl_up_sync(0xffffffff, x, o);
        if (lane >= o) x += t;
    }
    if (lane == 31) wsum[wid] = x;
    __syncthreads();
    if (wid == 0) {
        int s = wsum[lane];
        int y = s;
#pragma unroll
        for (int o = 1; o < 32; o <<= 1) {
            int t = __shfl_up_sync(0xffffffff, y, o);
            if (lane >= o) y += t;
        }
        wbase[lane] = y - s;
    }
    __syncthreads();
    if (i < M_NODES) off[i] = bbase[blockIdx.x] + wbase[wid] + x - v;
    if (i == 0) off[M_NODES] = NEDGE;
}

// fill CSR slots: eidx grouped by tgt, payload = (src<<3)|r
__global__ void fill_kernel(const int* __restrict__ edges, const int* __restrict__ off,
                            int* __restrict__ cursor, int* __restrict__ eidx)
{
    int i = blockIdx.x * 256 + threadIdx.x;
    if (i < NEDGE) {
        int r = i / EPR, e = i % EPR;
        int src = edges[r * 2 * EPR + e];
        int tgt = edges[r * 2 * EPR + EPR + e];
        int slot = off[tgt] + atomicAdd(&cursor[tgt], 1);
        eidx[slot] = (src << 3) | r;
    }
}

// ---------------- HMMA GEMM (R5/R7 mainloop; epilogue stores use .cs streaming) ----------------
__global__ __launch_bounds__(256, 2)
void gemm_mma(const __half* __restrict__ A, const __half* __restrict__ Wt,
              __half* __restrict__ msg)
{
    extern __shared__ unsigned char smraw[];
    const int tid  = threadIdx.x;
    const int lane = tid & 31;
    const int wid  = tid >> 5;
    const int wm   = wid & 3;
    const int wn   = wid >> 2;
    const int m0   = blockIdx.y * BM;
    const int n0   = blockIdx.x * BN;

    const int lrow = tid >> 3;
    const int lseg = tid & 7;

    int amrow[4];
#pragma unroll
    for (int p = 0; p < 4; p++) {
        int m = m0 + lrow + p * 32;
        amrow[p] = m < M_NODES ? m : M_NODES - 1;
    }

    float acc[2][8][4];
#pragma unroll
    for (int mi = 0; mi < 2; mi++)
#pragma unroll
        for (int ni = 0; ni < 8; ni++)
#pragma unroll
            for (int j = 0; j < 4; j++) acc[mi][ni][j] = 0.0f;

    unsigned aS[2], bS[2];
    aS[0] = su32(smraw);            bS[0] = su32(smraw + 16384);
    aS[1] = su32(smraw + 32768);    bS[1] = su32(smraw + 49152);

    auto issue = [&](int c, int st) {
        int koff = c * BK;
        unsigned char* As = smraw + st * 32768;
        unsigned char* Bs = smraw + st * 32768 + 16384;
#pragma unroll
        for (int p = 0; p < 4; p++) {
            int row = lrow + p * 32;
            unsigned so = swz((unsigned)(row * 128 + lseg * 16));
            cp16(As + so, A  + (size_t)amrow[p] * HID + koff + lseg * 8);
            cp16(Bs + so, Wt + (size_t)(n0 + row) * HID + koff + lseg * 8);
        }
        CP_COMMIT();
    };

    issue(0, 0);

    for (int c = 0; c < NCHUNK; ++c) {
        int st = c & 1;
        if (c + 1 < NCHUNK) { issue(c + 1, st ^ 1); CP_WAIT(1); }
        else                { CP_WAIT(0); }
        __syncthreads();

        unsigned ab = aS[st], bb = bS[st];
#pragma unroll
        for (int ks = 0; ks < 4; ++ks) {
            unsigned a[2][4], b[4][4];
#pragma unroll
            for (int mi = 0; mi < 2; mi++) {
                int row = wm * 32 + mi * 16 + (lane & 15);
                unsigned off = (unsigned)(row * 128 + ks * 32 + (lane >> 4) * 16);
                ldsm4(a[mi], ab + swz(off));
            }
#pragma unroll
            for (int nj = 0; nj < 4; nj++) {
                int q = lane >> 3, r = lane & 7;
                int nrow = wn * 64 + nj * 16 + (q >> 1) * 8 + r;
                unsigned off = (unsigned)(nrow * 128 + ks * 32 + (q & 1) * 16);
                ldsm4(b[nj], bb + swz(off));
            }
#pragma unroll
            for (int mi = 0; mi < 2; mi++)
#pragma unroll
                for (int ni = 0; ni < 8; ni++)
                    mma16816(acc[mi][ni], a[mi], b[ni >> 1][(ni & 1) * 2], b[ni >> 1][(ni & 1) * 2 + 1]);
        }
        __syncthreads();
    }

    // epilogue: streaming (.cs) stores — msg is write-once, keep A/Wt resident in L2
    const int cb = n0 + wn * 64 + (lane & 3) * 2;
#pragma unroll
    for (int mi = 0; mi < 2; mi++) {
        int r0 = m0 + wm * 32 + mi * 16 + (lane >> 2);
        int r1 = r0 + 8;
        if (r0 < M_NODES) {
            __half* dst = msg + (size_t)r0 * NMSG + cb;
#pragma unroll
            for (int ni = 0; ni < 8; ni++)
                __stcs((__half2*)(dst + ni * 8), __floats2half2_rn(acc[mi][ni][0], acc[mi][ni][1]));
        }
        if (r1 < M_NODES) {
            __half* dst = msg + (size_t)r1 * NMSG + cb;
#pragma unroll
            for (int ni = 0; ni < 8; ni++)
                __stcs((__half2*)(dst + ni * 8), __floats2half2_rn(acc[mi][ni][2], acc[mi][ni][3]));
        }
    }
}

// ---------------- gather + combine: warp per node, x4 unroll, .cs streaming loads ----------------
__global__ __launch_bounds__(256)
void gather_kernel(const __half* __restrict__ msg, const int* __restrict__ off,
                   const int* __restrict__ eidx, const float* __restrict__ invd,
                   const float* __restrict__ bias, __half* __restrict__ hout)
{
    int node = blockIdx.x * 8 + (threadIdx.x >> 5);
    if (node >= M_NODES) return;
    const int lane = threadIdx.x & 31;

    int beg = __ldg(&off[node]);
    int end = __ldg(&off[node + 1]);

    float acc[8];
#pragma unroll
    for (int j = 0; j < 8; j++) acc[j] = 0.0f;

    auto accum = [&](uint4 u) {
        const __half2* h2 = (const __half2*)&u;
#pragma unroll
        for (int k = 0; k < 4; k++) {
            float2 f = __half22float2(h2[k]);
            acc[2 * k]     += f.x;
            acc[2 * k + 1] += f.y;
        }
    };
    auto rowptr = [&](int pk) {
        return (const uint4*)(msg + (size_t)(pk >> 3) * NMSG + (pk & 7) * HID + lane * 8);
    };

    int e = beg;
    for (; e + 3 < end; e += 4) {
        uint4 u0 = __ldcs(rowptr(__ldg(&eidx[e])));
        uint4 u1 = __ldcs(rowptr(__ldg(&eidx[e + 1])));
        uint4 u2 = __ldcs(rowptr(__ldg(&eidx[e + 2])));
        uint4 u3 = __ldcs(rowptr(__ldg(&eidx[e + 3])));
        accum(u0); accum(u1); accum(u2); accum(u3);
    }
    for (; e < end; ++e)
        accum(__ldcs(rowptr(__ldg(&eidx[e]))));

    float w = invd[node];
    uint4 s = __ldcs((const uint4*)(msg + (size_t)node * NMSG + 1536 + lane * 8));
    const __half2* s2 = (const __half2*)&s;
    float4 b0 = *(const float4*)(bias + lane * 8);
    float4 b1 = *(const float4*)(bias + lane * 8 + 4);
    float bb[8] = {b0.x, b0.y, b0.z, b0.w, b1.x, b1.y, b1.z, b1.w};

    uint4 outv;
    __half2* o2 = (__half2*)&outv;
#pragma unroll
    for (int k = 0; k < 4; k++) {
        float2 sf = __half22float2(s2[k]);
        float v0 = fmaxf(acc[2 * k]     * w + sf.x + bb[2 * k],     0.f);
        float v1 = fmaxf(acc[2 * k + 1] * w + sf.y + bb[2 * k + 1], 0.f);
        o2[k] = __floats2half2_rn(v0, v1);
    }
    *(uint4*)(hout + (size_t)node * HID + lane * 8) = outv;
}

// Wt[n][k] fp16
__global__ void convW_kernel(const float* __restrict__ Wrel, const float* __restrict__ Wself,
                             __half* __restrict__ Wt)
{
    int idx = blockIdx.x * 256 + threadIdx.x;
    if (idx < NMSG * HID) {
        int n = idx >> 8, k = idx & 255;
        float v = (n < 1536) ? Wrel[(((n >> 8) * 256) + k) * 256 + (n & 255)]
                             : Wself[k * 256 + (n & 255)];
        Wt[idx] = __float2half_rn(v);
    }
}

// ---------------- pooling + MLP ----------------
__global__ void count_kernel(const int* __restrict__ bids, int* __restrict__ counts)
{
    int g = threadIdx.x;
    if (g >= NGRAPH) return;
    int lo = 0, hi = M_NODES;
    while (lo < hi) { int mid = (lo + hi) >> 1; if (bids[mid] < g) lo = mid + 1; else hi = mid; }
    int start = lo;
    lo = 0; hi = M_NODES;
    while (lo < hi) { int mid = (lo + hi) >> 1; if (bids[mid] <= g) lo = mid + 1; else hi = mid; }
    counts[g] = lo - start;
}

__global__ void pool_sum_kernel(const __half* __restrict__ h, const int* __restrict__ bids,
                                float* __restrict__ pooled)
{
    int c = threadIdx.x;
    int n_start = blockIdx.x * 256;
    int n_end = n_start + 256;
    if (n_end > M_NODES) n_end = M_NODES;
    if (n_start >= M_NODES) return;
    int cur = bids[n_start];
    float acc = 0.0f;
    for (int n = n_start; n < n_end; n++) {
        int g = bids[n];
        if (g != cur) { atomicAdd(&pooled[cur * HID + c], acc); acc = 0.0f; cur = g; }
        acc += __half2float(h[(size_t)n * HID + c]);
    }
    atomicAdd(&pooled[cur * HID + c], acc);
}

__global__ void mlp_kernel(const float* __restrict__ pooled, const int* __restrict__ counts,
                           const float* __restrict__ pW1, const float* __restrict__ pb1,
                           const float* __restrict__ pW2, const float* __restrict__ pb2,
                           float* __restrict__ out)
{
    __shared__ float p[HID];
    __shared__ float t[HID];
    int g = blockIdx.x, d = threadIdx.x;
    int cn = counts[g];
    float inv = 1.0f / (float)(cn > 1 ? cn : 1);
    p[d] = pooled[g * HID + d] * inv;
    __syncthreads();
    float a = pb1[d];
#pragma unroll 8
    for (int k = 0; k < HID; k++) a += p[k] * pW1[k * HID + d];
    t[d] = a > 0.f ? a : 0.f;
    __syncthreads();
    float o = pb2[d];
#pragma unroll 8
    for (int k = 0; k < HID; k++) o += t[k] * pW2[k * HID + d];
    out[g * HID + d] = o;
}

// ---------------------------------------------------------------
extern "C" void kernel_launch(void* const* d_in, const int* in_sizes, int n_in,
                              void* d_out, int out_size)
{
    const int*   x_type = (const int*)d_in[0];
    const int*   x_sub  = (const int*)d_in[1];
    const int*   edges  = (const int*)d_in[2];
    const int*   bids   = (const int*)d_in[3];
    const float* temb   = (const float*)d_in[5];
    const float* semb   = (const float*)d_in[6];
    const float* Wrel0  = (const float*)d_in[7];
    const float* Wself0 = (const float*)d_in[8];
    const float* b0     = (const float*)d_in[9];
    const float* Wrel1  = (const float*)d_in[10];
    const float* Wself1 = (const float*)d_in[11];
    const float* b1     = (const float*)d_in[12];
    const float* pW1    = (const float*)d_in[13];
    const float* pb1    = (const float*)d_in[14];
    const float* pW2    = (const float*)d_in[15];
    const float* pb2    = (const float*)d_in[16];
    float* out = (float*)d_out;

    void *phA, *phB, *pmsg, *pWt, *pinv, *pdeg, *poff, *pbsum, *pbbase, *pcur, *peidx, *ppooled, *pcnt;
    cudaGetSymbolAddress(&phA, g_hA16);
    cudaGetSymbolAddress(&phB, g_hB16);
    cudaGetSymbolAddress(&pmsg, g_msg);
    cudaGetSymbolAddress(&pWt, g_Wt);
    cudaGetSymbolAddress(&pinv, g_invdeg);
    cudaGetSymbolAddress(&pdeg, g_deg);
    cudaGetSymbolAddress(&poff, g_off);
    cudaGetSymbolAddress(&pbsum, g_bsum);
    cudaGetSymbolAddress(&pbbase, g_bbase);
    cudaGetSymbolAddress(&pcur, g_cursor);
    cudaGetSymbolAddress(&peidx, g_eidx);
    cudaGetSymbolAddress(&ppooled, g_pooled);
    cudaGetSymbolAddress(&pcnt, g_counts);

    cudaFuncSetAttribute(gemm_mma, cudaFuncAttributeMaxDynamicSharedMemorySize, GSMEM);

    cudaMemsetAsync(pdeg, 0, M_NODES * sizeof(int));
    cudaMemsetAsync(pcur, 0, M_NODES * sizeof(int));
    cudaMemsetAsync(ppooled, 0, NGRAPH * HID * sizeof(float));

    embed_kernel<<<(M_NODES * HID + 255) / 256, 256>>>(x_type, x_sub, temb, semb, (__half*)phA);
    degree_kernel<<<(NEDGE + 255) / 256, 256>>>(edges, (int*)pdeg);
    invdeg_kernel<<<(M_NODES + 255) / 256, 256>>>((const int*)pdeg, (float*)pinv);
    blocksum_kernel<<<NSCAN, SCAN_BLK>>>((const int*)pdeg, (int*)pbsum);
    bscan_kernel<<<1, 128>>>((const int*)pbsum, (int*)pbbase);
    offsets_kernel<<<NSCAN, SCAN_BLK>>>((const int*)pdeg, (const int*)pbbase, (int*)poff);
    fill_kernel<<<(NEDGE + 255) / 256, 256>>>(edges, (const int*)poff, (int*)pcur, (int*)peidx);

    dim3 ggrid(NMSG / BN, (M_NODES + BM - 1) / BM);   // (14, 782)
    int gblocks = (M_NODES + 7) / 8;

    // ---- layer 0: hA -> hB ----
    convW_kernel<<<(NMSG * HID + 255) / 256, 256>>>(Wrel0, Wself0, (__half*)pWt);
    gemm_mma<<<ggrid, 256, GSMEM>>>((const __half*)phA, (const __half*)pWt, (__half*)pmsg);
    gather_kernel<<<gblocks, 256>>>((const __half*)pmsg, (const int*)poff, (const int*)peidx,
                                    (const float*)pinv, b0, (__half*)phB);

    // ---- layer 1: hB -> hA ----
    convW_kernel<<<(NMSG * HID + 255) / 256, 256>>>(Wrel1, Wself1, (__half*)pWt);
    gemm_mma<<<ggrid, 256, GSMEM>>>((const __half*)phB, (const __half*)pWt, (__half*)pmsg);
    gather_kernel<<<gblocks, 256>>>((const __half*)pmsg, (const int*)poff, (const int*)peidx,
                                    (const float*)pinv, b1, (__half*)phA);

    // ---- pool + MLP ----
    count_kernel<<<1, 128>>>(bids, (int*)pcnt);
    pool_sum_kernel<<<(M_NODES + 255) / 256, 256>>>((const __half*)phA, bids, (float*)ppooled);
    mlp_kernel<<<NGRAPH, 256>>>((const float*)ppooled, (const int*)pcnt, pW1, pb1, pW2, pb2, out);
}

// round 10
// speedup vs baseline: 1.4527x; 1.2067x over previous
#include <cuda_runtime.h>
#include <cuda_fp16.h>

#define M_NODES 100000
#define HID     256
#define NREL    6
#define EPR     100000
#define NEDGE   (NREL * EPR)        // 600000
#define NMSG    1792                // 6*256 rel msgs + 256 self
#define NGRAPH  128

#define BM 128
#define BN 128
#define BK 64
#define NCHUNK (HID / BK)           // 4
#define GSMEM  (2 * (BM + BN) * BK * 2)   // 65536 (2-stage)

#define SCAN_BLK 1024
#define NSCAN1 ((M_NODES + SCAN_BLK - 1) / SCAN_BLK)  // 98
#define NBIN2  (NREL * M_NODES)                        // 600000
#define NSCAN2 ((NBIN2 + SCAN_BLK - 1) / SCAN_BLK)     // 586

// ---------------- scratch (device globals; no allocation allowed) ----------------
__device__ __half  g_hA16[(size_t)M_NODES * HID];
__device__ __half  g_hB16[(size_t)M_NODES * HID];
__device__ __half  g_msg[(size_t)M_NODES * NMSG];      // 358.4 MB
__device__ __half  g_Wt[NMSG * HID];
__device__ float   g_invdeg[M_NODES];
__device__ int     g_deg[M_NODES];
__device__ int     g_off[M_NODES + 1];
__device__ int     g_bsum1[NSCAN1];
__device__ int     g_bbase1[NSCAN1];
__device__ int     g_cursor[M_NODES];
__device__ int     g_eidx[NEDGE];                      // packed (src<<3)|r, grouped by tgt
__device__ int     g_flag[NBIN2];                      // (rel,node) has >=1 outgoing edge
__device__ int     g_soff[NBIN2 + 1];                  // exclusive scan of flags
__device__ int     g_bsum2[NSCAN2];
__device__ int     g_bbase2[NSCAN2];
__device__ int     g_rowlist[NBIN2];                   // active nodes, grouped by rel
__device__ float   g_pooled[NGRAPH * HID];
__device__ int     g_counts[NGRAPH];

// ---------------- PTX helpers (baseline ISA; nothing 'a'-gated) ----------------
__device__ __forceinline__ unsigned su32(const void* p) {
    return (unsigned)__cvta_generic_to_shared(p);
}
__device__ __forceinline__ void cp16(void* sm, const void* gm) {
    asm volatile("cp.async.cg.shared.global [%0], [%1], 16;" :: "r"(su32(sm)), "l"(gm));
}
#define CP_COMMIT() asm volatile("cp.async.commit_group;" ::: "memory")
#define CP_WAIT(n)  asm volatile("cp.async.wait_group %0;" :: "n"(n) : "memory")

__device__ __forceinline__ void ldsm4(unsigned* r, unsigned addr) {
    asm volatile("ldmatrix.sync.aligned.m8n8.x4.shared.b16 {%0,%1,%2,%3}, [%4];"
                 : "=r"(r[0]), "=r"(r[1]), "=r"(r[2]), "=r"(r[3]) : "r"(addr));
}
__device__ __forceinline__ void mma16816(float* c, const unsigned* a, unsigned b0, unsigned b1) {
    asm volatile("mma.sync.aligned.m16n8k16.row.col.f32.f16.f16.f32 "
                 "{%0,%1,%2,%3}, {%4,%5,%6,%7}, {%8,%9}, {%0,%1,%2,%3};"
                 : "+f"(c[0]), "+f"(c[1]), "+f"(c[2]), "+f"(c[3])
                 : "r"(a[0]), "r"(a[1]), "r"(a[2]), "r"(a[3]), "r"(b0), "r"(b1));
}
__device__ __forceinline__ unsigned swz(unsigned off) {
    return off ^ ((off >> 3) & 0x70);
}

// ---------------- small kernels ----------------
__global__ void embed_kernel(const int* __restrict__ x_type, const int* __restrict__ x_sub,
                             const float* __restrict__ temb, const float* __restrict__ semb,
                             __half* __restrict__ h0)
{
    int gid = blockIdx.x * 256 + threadIdx.x;
    if (gid < M_NODES * HID) {
        int n = gid >> 8, c = gid & 255;
        float v = (c < 128) ? temb[x_type[n] * 128 + c] : semb[x_sub[n] * 128 + (c - 128)];
        h0[gid] = __float2half_rn(v);
    }
}

__global__ void degree_kernel(const int* __restrict__ edges, int* __restrict__ deg)
{
    int i = blockIdx.x * 256 + threadIdx.x;
    if (i < NEDGE) {
        int r = i / EPR, e = i % EPR;
        atomicAdd(&deg[edges[r * 2 * EPR + EPR + e]], 1);
    }
}

__global__ void invdeg_kernel(const int* __restrict__ deg, float* __restrict__ invd)
{
    int i = blockIdx.x * 256 + threadIdx.x;
    if (i < M_NODES) {
        int d = deg[i];
        invd[i] = 1.0f / (float)(d > 1 ? d : 1);
    }
}

// mark (rel, src) bins with at least one edge
__global__ void flag_kernel(const int* __restrict__ edges, int* __restrict__ flag)
{
    int i = blockIdx.x * 256 + threadIdx.x;
    if (i < NEDGE) {
        int r = i / EPR, e = i % EPR;
        int src = edges[r * 2 * EPR + e];
        flag[r * M_NODES + src] = 1;
    }
}

// ---- generic 3-phase exclusive scan (n parameterized) ----
__global__ void blocksum_kernel(const int* __restrict__ v_in, int* __restrict__ bsum, int n)
{
    __shared__ int ws[32];
    int i = blockIdx.x * SCAN_BLK + threadIdx.x;
    int v = (i < n) ? v_in[i] : 0;
#pragma unroll
    for (int o = 16; o; o >>= 1) v += __shfl_down_sync(0xffffffff, v, o);
    if ((threadIdx.x & 31) == 0) ws[threadIdx.x >> 5] = v;
    __syncthreads();
    if (threadIdx.x < 32) {
        int s = ws[threadIdx.x];
#pragma unroll
        for (int o = 16; o; o >>= 1) s += __shfl_down_sync(0xffffffff, s, o);
        if (threadIdx.x == 0) bsum[blockIdx.x] = s;
    }
}

__global__ void bscan_kernel(const int* __restrict__ bsum, int* __restrict__ bbase, int n)
{
    // n <= 1024, one block of 1024
    __shared__ int wsum[32];
    __shared__ int wbase[32];
    int tid = threadIdx.x, lane = tid & 31, wid = tid >> 5;
    int v = (tid < n) ? bsum[tid] : 0;
    int x = v;
#pragma unroll
    for (int o = 1; o < 32; o <<= 1) {
        int t = __shfl_up_sync(0xffffffff, x, o);
        if (lane >= o) x += t;
    }
    if (lane == 31) wsum[wid] = x;
    __syncthreads();
    if (wid == 0) {
        int s = wsum[lane];
        int y = s;
#pragma unroll
        for (int o = 1; o < 32; o <<= 1) {
            int t = __shfl_up_sync(0xffffffff, y, o);
            if (lane >= o) y += t;
        }
        wbase[lane] = y - s;
    }
    __syncthreads();
    if (tid < n) bbase[tid] = wbase[wid] + x - v;
}

__global__ void offsets_kernel(const int* __restrict__ v_in, const int* __restrict__ bbase,
                               int* __restrict__ off, int n)
{
    __shared__ int wsum[32];
    __shared__ int wbase[32];
    int i = blockIdx.x * SCAN_BLK + threadIdx.x;
    int lane = threadIdx.x & 31, wid = threadIdx.x >> 5;
    int v = (i < n) ? v_in[i] : 0;
    int x = v;
#pragma unroll
    for (int o = 1; o < 32; o <<= 1) {
        int t = __shfl_up_sync(0xffffffff, x, o);
        if (lane >= o) x += t;
    }
    if (lane == 31) wsum[wid] = x;
    __syncthreads();
    if (wid == 0) {
        int s = wsum[lane];
        int y = s;
#pragma unroll
        for (int o = 1; o < 32; o <<= 1) {
            int t = __shfl_up_sync(0xffffffff, y, o);
            if (lane >= o) y += t;
        }
        wbase[lane] = y - s;
    }
    __syncthreads();
    if (i < n) off[i] = bbase[blockIdx.x] + wbase[wid] + x - v;
    if (i == n - 1) off[n] = bbase[blockIdx.x] + wbase[wid] + x;   // inclusive total
}

// fill CSR slots: eidx grouped by tgt, payload = (src<<3)|r
__global__ void fill_kernel(const int* __restrict__ edges, const int* __restrict__ off,
                            int* __restrict__ cursor, int* __restrict__ eidx)
{
    int i = blockIdx.x * 256 + threadIdx.x;
    if (i < NEDGE) {
        int r = i / EPR, e = i % EPR;
        int src = edges[r * 2 * EPR + e];
        int tgt = edges[r * 2 * EPR + EPR + e];
        int slot = off[tgt] + atomicAdd(&cursor[tgt], 1);
        eidx[slot] = (src << 3) | r;
    }
}

// compact active nodes per rel: rowlist[soff[i]] = node  (i = r*M + node)
__global__ void rowlist_kernel(const int* __restrict__ flag, const int* __restrict__ soff,
                               int* __restrict__ rowlist)
{
    int i = blockIdx.x * 256 + threadIdx.x;
    if (i < NBIN2 && flag[i])
        rowlist[soff[i]] = i % M_NODES;
}

// Wt[n][k] fp16
__global__ void convW_kernel(const float* __restrict__ Wrel, const float* __restrict__ Wself,
                             __half* __restrict__ Wt)
{
    int idx = blockIdx.x * 256 + threadIdx.x;
    if (idx < NMSG * HID) {
        int n = idx >> 8, k = idx & 255;
        float v = (n < 1536) ? Wrel[(((n >> 8) * 256) + k) * 256 + (n & 255)]
                             : Wself[k * 256 + (n & 255)];
        Wt[idx] = __float2half_rn(v);
    }
}

// ---------------- rel GEMM: compacted rows, grid (2, 782, 6) ----------------
// msg[row, r*256 + n] = h[row] @ Wrel_r  for active rows only
__global__ __launch_bounds__(256, 2)
void gemm_rel(const __half* __restrict__ A, const __half* __restrict__ Wt,
              const int* __restrict__ soff, const int* __restrict__ rowlist,
              __half* __restrict__ msg)
{
    extern __shared__ unsigned char smraw[];
    const int rrel = blockIdx.z;
    const int base = __ldg(&soff[rrel * M_NODES]);
    const int cnt  = __ldg(&soff[(rrel + 1) * M_NODES]) - base;
    const int m0   = blockIdx.y * BM;
    if (m0 >= cnt) return;

    const int tid  = threadIdx.x;
    const int lane = tid & 31;
    const int wid  = tid >> 5;
    const int wm   = wid & 3;
    const int wn   = wid >> 2;
    const int n0   = blockIdx.x * BN;      // 0 or 128 within the rel's 256 cols

    const int lrow = tid >> 3;
    const int lseg = tid & 7;

    int amrow[4];
#pragma unroll
    for (int p = 0; p < 4; p++) {
        int idx = m0 + lrow + p * 32;
        if (idx >= cnt) idx = cnt - 1;
        amrow[p] = __ldg(&rowlist[base + idx]);
    }

    float acc[2][8][4];
#pragma unroll
    for (int mi = 0; mi < 2; mi++)
#pragma unroll
        for (int ni = 0; ni < 8; ni++)
#pragma unroll
            for (int j = 0; j < 4; j++) acc[mi][ni][j] = 0.0f;

    unsigned aS[2], bS[2];
    aS[0] = su32(smraw);            bS[0] = su32(smraw + 16384);
    aS[1] = su32(smraw + 32768);    bS[1] = su32(smraw + 49152);

    auto issue = [&](int c, int st) {
        int koff = c * BK;
        unsigned char* As = smraw + st * 32768;
        unsigned char* Bs = smraw + st * 32768 + 16384;
#pragma unroll
        for (int p = 0; p < 4; p++) {
            int row = lrow + p * 32;
            unsigned so = swz((unsigned)(row * 128 + lseg * 16));
            cp16(As + so, A  + (size_t)amrow[p] * HID + koff + lseg * 8);
            cp16(Bs + so, Wt + (size_t)(rrel * 256 + n0 + row) * HID + koff + lseg * 8);
        }
        CP_COMMIT();
    };

    issue(0, 0);

    for (int c = 0; c < NCHUNK; ++c) {
        int st = c & 1;
        if (c + 1 < NCHUNK) { issue(c + 1, st ^ 1); CP_WAIT(1); }
        else                { CP_WAIT(0); }
        __syncthreads();

        unsigned ab = aS[st], bb = bS[st];
#pragma unroll
        for (int ks = 0; ks < 4; ++ks) {
            unsigned a[2][4], b[4][4];
#pragma unroll
            for (int mi = 0; mi < 2; mi++) {
                int row = wm * 32 + mi * 16 + (lane & 15);
                unsigned off = (unsigned)(row * 128 + ks * 32 + (lane >> 4) * 16);
                ldsm4(a[mi], ab + swz(off));
            }
#pragma unroll
            for (int nj = 0; nj < 4; nj++) {
                int q = lane >> 3, r2 = lane & 7;
                int nrow = wn * 64 + nj * 16 + (q >> 1) * 8 + r2;
                unsigned off = (unsigned)(nrow * 128 + ks * 32 + (q & 1) * 16);
                ldsm4(b[nj], bb + swz(off));
            }
#pragma unroll
            for (int mi = 0; mi < 2; mi++)
#pragma unroll
                for (int ni = 0; ni < 8; ni++)
                    mma16816(acc[mi][ni], a[mi], b[ni >> 1][(ni & 1) * 2], b[ni >> 1][(ni & 1) * 2 + 1]);
        }
        __syncthreads();
    }

    const int cb = rrel * 256 + n0 + wn * 64 + (lane & 3) * 2;
#pragma unroll
    for (int mi = 0; mi < 2; mi++) {
        int r0 = m0 + wm * 32 + mi * 16 + (lane >> 2);
        int r1 = r0 + 8;
        if (r0 < cnt) {
            int grow = __ldg(&rowlist[base + r0]);
            __half* dst = msg + (size_t)grow * NMSG + cb;
#pragma unroll
            for (int ni = 0; ni < 8; ni++)
                __stcs((__half2*)(dst + ni * 8), __floats2half2_rn(acc[mi][ni][0], acc[mi][ni][1]));
        }
        if (r1 < cnt) {
            int grow = __ldg(&rowlist[base + r1]);
            __half* dst = msg + (size_t)grow * NMSG + cb;
#pragma unroll
            for (int ni = 0; ni < 8; ni++)
                __stcs((__half2*)(dst + ni * 8), __floats2half2_rn(acc[mi][ni][2], acc[mi][ni][3]));
        }
    }
}

// ---------------- self GEMM: dense rows, cols 1536..1791, grid (2, 782) ----------------
__global__ __launch_bounds__(256, 2)
void gemm_self(const __half* __restrict__ A, const __half* __restrict__ Wt,
               __half* __restrict__ msg)
{
    extern __shared__ unsigned char smraw[];
    const int tid  = threadIdx.x;
    const int lane = tid & 31;
    const int wid  = tid >> 5;
    const int wm   = wid & 3;
    const int wn   = wid >> 2;
    const int m0   = blockIdx.y * BM;
    const int n0   = blockIdx.x * BN;      // 0 or 128 within self's 256 cols

    const int lrow = tid >> 3;
    const int lseg = tid & 7;

    int amrow[4];
#pragma unroll
    for (int p = 0; p < 4; p++) {
        int m = m0 + lrow + p * 32;
        amrow[p] = m < M_NODES ? m : M_NODES - 1;
    }

    float acc[2][8][4];
#pragma unroll
    for (int mi = 0; mi < 2; mi++)
#pragma unroll
        for (int ni = 0; ni < 8; ni++)
#pragma unroll
            for (int j = 0; j < 4; j++) acc[mi][ni][j] = 0.0f;

    unsigned aS[2], bS[2];
    aS[0] = su32(smraw);            bS[0] = su32(smraw + 16384);
    aS[1] = su32(smraw + 32768);    bS[1] = su32(smraw + 49152);

    auto issue = [&](int c, int st) {
        int koff = c * BK;
        unsigned char* As = smraw + st * 32768;
        unsigned char* Bs = smraw + st * 32768 + 16384;
#pragma unroll
        for (int p = 0; p < 4; p++) {
            int row = lrow + p * 32;
            unsigned so = swz((unsigned)(row * 128 + lseg * 16));
            cp16(As + so, A  + (size_t)amrow[p] * HID + koff + lseg * 8);
            cp16(Bs + so, Wt + (size_t)(1536 + n0 + row) * HID + koff + lseg * 8);
        }
        CP_COMMIT();
    };

    issue(0, 0);

    for (int c = 0; c < NCHUNK; ++c) {
        int st = c & 1;
        if (c + 1 < NCHUNK) { issue(c + 1, st ^ 1); CP_WAIT(1); }
        else                { CP_WAIT(0); }
        __syncthreads();

        unsigned ab = aS[st], bb = bS[st];
#pragma unroll
        for (int ks = 0; ks < 4; ++ks) {
            unsigned a[2][4], b[4][4];
#pragma unroll
            for (int mi = 0; mi < 2; mi++) {
                int row = wm * 32 + mi * 16 + (lane & 15);
                unsigned off = (unsigned)(row * 128 + ks * 32 + (lane >> 4) * 16);
                ldsm4(a[mi], ab + swz(off));
            }
#pragma unroll
            for (int nj = 0; nj < 4; nj++) {
                int q = lane >> 3, r2 = lane & 7;
                int nrow = wn * 64 + nj * 16 + (q >> 1) * 8 + r2;
                unsigned off = (unsigned)(nrow * 128 + ks * 32 + (q & 1) * 16);
                ldsm4(b[nj], bb + swz(off));
            }
#pragma unroll
            for (int mi = 0; mi < 2; mi++)
#pragma unroll
                for (int ni = 0; ni < 8; ni++)
                    mma16816(acc[mi][ni], a[mi], b[ni >> 1][(ni & 1) * 2], b[ni >> 1][(ni & 1) * 2 + 1]);
        }
        __syncthreads();
    }

    const int cb = 1536 + n0 + wn * 64 + (lane & 3) * 2;
#pragma unroll
    for (int mi = 0; mi < 2; mi++) {
        int r0 = m0 + wm * 32 + mi * 16 + (lane >> 2);
        int r1 = r0 + 8;
        if (r0 < M_NODES) {
            __half* dst = msg + (size_t)r0 * NMSG + cb;
#pragma unroll
            for (int ni = 0; ni < 8; ni++)
                __stcs((__half2*)(dst + ni * 8), __floats2half2_rn(acc[mi][ni][0], acc[mi][ni][1]));
        }
        if (r1 < M_NODES) {
            __half* dst = msg + (size_t)r1 * NMSG + cb;
#pragma unroll
            for (int ni = 0; ni < 8; ni++)
                __stcs((__half2*)(dst + ni * 8), __floats2half2_rn(acc[mi][ni][2], acc[mi][ni][3]));
        }
    }
}

// ---------------- gather + combine: warp per node, x4 unroll, .cs streaming loads ----------------
__global__ __launch_bounds__(256)
void gather_kernel(const __half* __restrict__ msg, const int* __restrict__ off,
                   const int* __restrict__ eidx, const float* __restrict__ invd,
                   const float* __restrict__ bias, __half* __restrict__ hout)
{
    int node = blockIdx.x * 8 + (threadIdx.x >> 5);
    if (node >= M_NODES) return;
    const int lane = threadIdx.x & 31;

    int beg = __ldg(&off[node]);
    int end = __ldg(&off[node + 1]);

    float acc[8];
#pragma unroll
    for (int j = 0; j < 8; j++) acc[j] = 0.0f;

    auto accum = [&](uint4 u) {
        const __half2* h2 = (const __half2*)&u;
#pragma unroll
        for (int k = 0; k < 4; k++) {
            float2 f = __half22float2(h2[k]);
            acc[2 * k]     += f.x;
            acc[2 * k + 1] += f.y;
        }
    };
    auto rowptr = [&](int pk) {
        return (const uint4*)(msg + (size_t)(pk >> 3) * NMSG + (pk & 7) * HID + lane * 8);
    };

    int e = beg;
    for (; e + 3 < end; e += 4) {
        uint4 u0 = __ldcs(rowptr(__ldg(&eidx[e])));
        uint4 u1 = __ldcs(rowptr(__ldg(&eidx[e + 1])));
        uint4 u2 = __ldcs(rowptr(__ldg(&eidx[e + 2])));
        uint4 u3 = __ldcs(rowptr(__ldg(&eidx[e + 3])));
        accum(u0); accum(u1); accum(u2); accum(u3);
    }
    for (; e < end; ++e)
        accum(__ldcs(rowptr(__ldg(&eidx[e]))));

    float w = invd[node];
    uint4 s = __ldcs((const uint4*)(msg + (size_t)node * NMSG + 1536 + lane * 8));
    const __half2* s2 = (const __half2*)&s;
    float4 b0 = *(const float4*)(bias + lane * 8);
    float4 b1 = *(const float4*)(bias + lane * 8 + 4);
    float bb[8] = {b0.x, b0.y, b0.z, b0.w, b1.x, b1.y, b1.z, b1.w};

    uint4 outv;
    __half2* o2 = (__half2*)&outv;
#pragma unroll
    for (int k = 0; k < 4; k++) {
        float2 sf = __half22float2(s2[k]);
        float v0 = fmaxf(acc[2 * k]     * w + sf.x + bb[2 * k],     0.f);
        float v1 = fmaxf(acc[2 * k + 1] * w + sf.y + bb[2 * k + 1], 0.f);
        o2[k] = __floats2half2_rn(v0, v1);
    }
    *(uint4*)(hout + (size_t)node * HID + lane * 8) = outv;
}

// ---------------- pooling + MLP ----------------
__global__ void count_kernel(const int* __restrict__ bids, int* __restrict__ counts)
{
    int g = threadIdx.x;
    if (g >= NGRAPH) return;
    int lo = 0, hi = M_NODES;
    while (lo < hi) { int mid = (lo + hi) >> 1; if (bids[mid] < g) lo = mid + 1; else hi = mid; }
    int start = lo;
    lo = 0; hi = M_NODES;
    while (lo < hi) { int mid = (lo + hi) >> 1; if (bids[mid] <= g) lo = mid + 1; else hi = mid; }
    counts[g] = lo - start;
}

__global__ void pool_sum_kernel(const __half* __restrict__ h, const int* __restrict__ bids,
                                float* __restrict__ pooled)
{
    int c = threadIdx.x;
    int n_start = blockIdx.x * 256;
    int n_end = n_start + 256;
    if (n_end > M_NODES) n_end = M_NODES;
    if (n_start >= M_NODES) return;
    int cur = bids[n_start];
    float acc = 0.0f;
    for (int n = n_start; n < n_end; n++) {
        int g = bids[n];
        if (g != cur) { atomicAdd(&pooled[cur * HID + c], acc); acc = 0.0f; cur = g; }
        acc += __half2float(h[(size_t)n * HID + c]);
    }
    atomicAdd(&pooled[cur * HID + c], acc);
}

__global__ void mlp_kernel(const float* __restrict__ pooled, const int* __restrict__ counts,
                           const float* __restrict__ pW1, const float* __restrict__ pb1,
                           const float* __restrict__ pW2, const float* __restrict__ pb2,
                           float* __restrict__ out)
{
    __shared__ float p[HID];
    __shared__ float t[HID];
    int g = blockIdx.x, d = threadIdx.x;
    int cn = counts[g];
    float inv = 1.0f / (float)(cn > 1 ? cn : 1);
    p[d] = pooled[g * HID + d] * inv;
    __syncthreads();
    float a = pb1[d];
#pragma unroll 8
    for (int k = 0; k < HID; k++) a += p[k] * pW1[k * HID + d];
    t[d] = a > 0.f ? a : 0.f;
    __syncthreads();
    float o = pb2[d];
#pragma unroll 8
    for (int k = 0; k < HID; k++) o += t[k] * pW2[k * HID + d];
    out[g * HID + d] = o;
}

// ---------------------------------------------------------------
extern "C" void kernel_launch(void* const* d_in, const int* in_sizes, int n_in,
                              void* d_out, int out_size)
{
    const int*   x_type = (const int*)d_in[0];
    const int*   x_sub  = (const int*)d_in[1];
    const int*   edges  = (const int*)d_in[2];
    const int*   bids   = (const int*)d_in[3];
    const float* temb   = (const float*)d_in[5];
    const float* semb   = (const float*)d_in[6];
    const float* Wrel0  = (const float*)d_in[7];
    const float* Wself0 = (const float*)d_in[8];
    const float* b0     = (const float*)d_in[9];
    const float* Wrel1  = (const float*)d_in[10];
    const float* Wself1 = (const float*)d_in[11];
    const float* b1     = (const float*)d_in[12];
    const float* pW1    = (const float*)d_in[13];
    const float* pb1    = (const float*)d_in[14];
    const float* pW2    = (const float*)d_in[15];
    const float* pb2    = (const float*)d_in[16];
    float* out = (float*)d_out;

    void *phA, *phB, *pmsg, *pWt, *pinv, *pdeg, *poff, *pbsum1, *pbbase1, *pcur, *peidx;
    void *pflag, *psoff, *pbsum2, *pbbase2, *prowlist, *ppooled, *pcnt;
    cudaGetSymbolAddress(&phA, g_hA16);
    cudaGetSymbolAddress(&phB, g_hB16);
    cudaGetSymbolAddress(&pmsg, g_msg);
    cudaGetSymbolAddress(&pWt, g_Wt);
    cudaGetSymbolAddress(&pinv, g_invdeg);
    cudaGetSymbolAddress(&pdeg, g_deg);
    cudaGetSymbolAddress(&poff, g_off);
    cudaGetSymbolAddress(&pbsum1, g_bsum1);
    cudaGetSymbolAddress(&pbbase1, g_bbase1);
    cudaGetSymbolAddress(&pcur, g_cursor);
    cudaGetSymbolAddress(&peidx, g_eidx);
    cudaGetSymbolAddress(&pflag, g_flag);
    cudaGetSymbolAddress(&psoff, g_soff);
    cudaGetSymbolAddress(&pbsum2, g_bsum2);
    cudaGetSymbolAddress(&pbbase2, g_bbase2);
    cudaGetSymbolAddress(&prowlist, g_rowlist);
    cudaGetSymbolAddress(&ppooled, g_pooled);
    cudaGetSymbolAddress(&pcnt, g_counts);

    cudaFuncSetAttribute(gemm_rel, cudaFuncAttributeMaxDynamicSharedMemorySize, GSMEM);
    cudaFuncSetAttribute(gemm_self, cudaFuncAttributeMaxDynamicSharedMemorySize, GSMEM);

    cudaMemsetAsync(pdeg, 0, M_NODES * sizeof(int));
    cudaMemsetAsync(pcur, 0, M_NODES * sizeof(int));
    cudaMemsetAsync(pflag, 0, NBIN2 * sizeof(int));
    cudaMemsetAsync(ppooled, 0, NGRAPH * HID * sizeof(float));

    embed_kernel<<<(M_NODES * HID + 255) / 256, 256>>>(x_type, x_sub, temb, semb, (__half*)phA);

    // CSR by tgt (gather)
    degree_kernel<<<(NEDGE + 255) / 256, 256>>>(edges, (int*)pdeg);
    invdeg_kernel<<<(M_NODES + 255) / 256, 256>>>((const int*)pdeg, (float*)pinv);
    blocksum_kernel<<<NSCAN1, SCAN_BLK>>>((const int*)pdeg, (int*)pbsum1, M_NODES);
    bscan_kernel<<<1, SCAN_BLK>>>((const int*)pbsum1, (int*)pbbase1, NSCAN1);
    offsets_kernel<<<NSCAN1, SCAN_BLK>>>((const int*)pdeg, (const int*)pbbase1, (int*)poff, M_NODES);
    fill_kernel<<<(NEDGE + 255) / 256, 256>>>(edges, (const int*)poff, (int*)pcur, (int*)peidx);

    // compacted (rel, src) row lists for the rel-GEMMs
    flag_kernel<<<(NEDGE + 255) / 256, 256>>>(edges, (int*)pflag);
    blocksum_kernel<<<NSCAN2, SCAN_BLK>>>((const int*)pflag, (int*)pbsum2, NBIN2);
    bscan_kernel<<<1, SCAN_BLK>>>((const int*)pbsum2, (int*)pbbase2, NSCAN2);
    offsets_kernel<<<NSCAN2, SCAN_BLK>>>((const int*)pflag, (const int*)pbbase2, (int*)psoff, NBIN2);
    rowlist_kernel<<<(NBIN2 + 255) / 256, 256>>>((const int*)pflag, (const int*)psoff, (int*)prowlist);

    dim3 rgrid(2, (M_NODES + BM - 1) / BM, NREL);   // (2, 782, 6), early-exit above cnt
    dim3 sgrid(2, (M_NODES + BM - 1) / BM);         // (2, 782)
    int gblocks = (M_NODES + 7) / 8;

    // ---- layer 0: hA -> hB ----
    convW_kernel<<<(NMSG * HID + 255) / 256, 256>>>(Wrel0, Wself0, (__half*)pWt);
    gemm_rel<<<rgrid, 256, GSMEM>>>((const __half*)phA, (const __half*)pWt,
                                    (const int*)psoff, (const int*)prowlist, (__half*)pmsg);
    gemm_self<<<sgrid, 256, GSMEM>>>((const __half*)phA, (const __half*)pWt, (__half*)pmsg);
    gather_kernel<<<gblocks, 256>>>((const __half*)pmsg, (const int*)poff, (const int*)peidx,
                                    (const float*)pinv, b0, (__half*)phB);

    // ---- layer 1: hB -> hA ----
    convW_kernel<<<(NMSG * HID + 255) / 256, 256>>>(Wrel1, Wself1, (__half*)pWt);
    gemm_rel<<<rgrid, 256, GSMEM>>>((const __half*)phB, (const __half*)pWt,
                                    (const int*)psoff, (const int*)prowlist, (__half*)pmsg);
    gemm_self<<<sgrid, 256, GSMEM>>>((const __half*)phB, (const __half*)pWt, (__half*)pmsg);
    gather_kernel<<<gblocks, 256>>>((const __half*)pmsg, (const int*)poff, (const int*)peidx,
                                    (const float*)pinv, b1, (__half*)phA);

    // ---- pool + MLP ----
    count_kernel<<<1, 128>>>(bids, (int*)pcnt);
    pool_sum_kernel<<<(M_NODES + 255) / 256, 256>>>((const __half*)phA, bids, (float*)ppooled);
    mlp_kernel<<<NGRAPH, 256>>>((const float*)ppooled, (const int*)pcnt, pW1, pb1, pW2, pb2, out);
}

// round 11
// speedup vs baseline: 1.4822x; 1.0203x over previous
#include <cuda_runtime.h>
#include <cuda_fp16.h>

#define M_NODES 100000
#define HID     256
#define NREL    6
#define EPR     100000
#define NEDGE   (NREL * EPR)        // 600000
#define NMSG    1792                // 6*256 rel msgs + 256 self
#define NGRAPH  128

#define BM 128
#define BN 128
#define BK 64
#define NCHUNK (HID / BK)           // 4
#define GSMEM  (2 * (BM + BN) * BK * 2)   // 65536 (2-stage)

#define SCAN_BLK 1024
#define NSCAN1 ((M_NODES + SCAN_BLK - 1) / SCAN_BLK)  // 98
#define NBIN2  (NREL * M_NODES)                        // 600000
#define NSCAN2 ((NBIN2 + SCAN_BLK - 1) / SCAN_BLK)     // 586

// ---------------- scratch (device globals; no allocation allowed) ----------------
__device__ __half  g_hA16[(size_t)M_NODES * HID];
__device__ __half  g_hB16[(size_t)M_NODES * HID];
__device__ __half  g_msg[(size_t)M_NODES * NMSG];      // 358.4 MB
__device__ __half  g_Wt0[NMSG * HID];
__device__ __half  g_Wt1[NMSG * HID];
__device__ float   g_invdeg[M_NODES];
__device__ int     g_deg[M_NODES];
__device__ int     g_off[M_NODES + 1];
__device__ int     g_bsum1[NSCAN1];
__device__ int     g_bbase1[NSCAN1];
__device__ int     g_cursor[M_NODES];
__device__ int     g_eidx[NEDGE];                      // packed (src<<3)|r, grouped by tgt
__device__ int     g_flag[NBIN2];                      // (rel,node) has >=1 outgoing edge
__device__ int     g_soff[NBIN2 + 1];                  // exclusive scan of flags
__device__ int     g_bsum2[NSCAN2];
__device__ int     g_bbase2[NSCAN2];
__device__ int     g_rowlist[NBIN2];                   // active nodes, grouped by rel
__device__ float   g_pooled[NGRAPH * HID];
__device__ int     g_counts[NGRAPH];

// ---------------- PTX helpers (baseline ISA; nothing 'a'-gated) ----------------
__device__ __forceinline__ unsigned su32(const void* p) {
    return (unsigned)__cvta_generic_to_shared(p);
}
__device__ __forceinline__ void cp16(void* sm, const void* gm) {
    asm volatile("cp.async.cg.shared.global [%0], [%1], 16;" :: "r"(su32(sm)), "l"(gm));
}
#define CP_COMMIT() asm volatile("cp.async.commit_group;" ::: "memory")
#define CP_WAIT(n)  asm volatile("cp.async.wait_group %0;" :: "n"(n) : "memory")

__device__ __forceinline__ void ldsm4(unsigned* r, unsigned addr) {
    asm volatile("ldmatrix.sync.aligned.m8n8.x4.shared.b16 {%0,%1,%2,%3}, [%4];"
                 : "=r"(r[0]), "=r"(r[1]), "=r"(r[2]), "=r"(r[3]) : "r"(addr));
}
__device__ __forceinline__ void mma16816(float* c, const unsigned* a, unsigned b0, unsigned b1) {
    asm volatile("mma.sync.aligned.m16n8k16.row.col.f32.f16.f16.f32 "
                 "{%0,%1,%2,%3}, {%4,%5,%6,%7}, {%8,%9}, {%0,%1,%2,%3};"
                 : "+f"(c[0]), "+f"(c[1]), "+f"(c[2]), "+f"(c[3])
                 : "r"(a[0]), "r"(a[1]), "r"(a[2]), "r"(a[3]), "r"(b0), "r"(b1));
}
__device__ __forceinline__ unsigned swz(unsigned off) {
    return off ^ ((off >> 3) & 0x70);
}

// ---------------- small kernels ----------------
__global__ void embed_kernel(const int* __restrict__ x_type, const int* __restrict__ x_sub,
                             const float* __restrict__ temb, const float* __restrict__ semb,
                             __half* __restrict__ h0)
{
    int gid = blockIdx.x * 256 + threadIdx.x;
    if (gid < M_NODES * HID) {
        int n = gid >> 8, c = gid & 255;
        float v = (c < 128) ? temb[x_type[n] * 128 + c] : semb[x_sub[n] * 128 + (c - 128)];
        h0[gid] = __float2half_rn(v);
    }
}

// fused: in-degree count (by tgt) + outgoing-activity flag (by rel,src), one edge pass
__global__ void degflag_kernel(const int* __restrict__ edges, int* __restrict__ deg,
                               int* __restrict__ flag)
{
    int i = blockIdx.x * 256 + threadIdx.x;
    if (i < NEDGE) {
        int r = i / EPR, e = i % EPR;
        int src = edges[r * 2 * EPR + e];
        int tgt = edges[r * 2 * EPR + EPR + e];
        atomicAdd(&deg[tgt], 1);
        flag[r * M_NODES + src] = 1;
    }
}

__global__ void invdeg_kernel(const int* __restrict__ deg, float* __restrict__ invd)
{
    int i = blockIdx.x * 256 + threadIdx.x;
    if (i < M_NODES) {
        int d = deg[i];
        invd[i] = 1.0f / (float)(d > 1 ? d : 1);
    }
}

// ---- generic 3-phase exclusive scan (n parameterized) ----
__global__ void blocksum_kernel(const int* __restrict__ v_in, int* __restrict__ bsum, int n)
{
    __shared__ int ws[32];
    int i = blockIdx.x * SCAN_BLK + threadIdx.x;
    int v = (i < n) ? v_in[i] : 0;
#pragma unroll
    for (int o = 16; o; o >>= 1) v += __shfl_down_sync(0xffffffff, v, o);
    if ((threadIdx.x & 31) == 0) ws[threadIdx.x >> 5] = v;
    __syncthreads();
    if (threadIdx.x < 32) {
        int s = ws[threadIdx.x];
#pragma unroll
        for (int o = 16; o; o >>= 1) s += __shfl_down_sync(0xffffffff, s, o);
        if (threadIdx.x == 0) bsum[blockIdx.x] = s;
    }
}

__global__ void bscan_kernel(const int* __restrict__ bsum, int* __restrict__ bbase, int n)
{
    __shared__ int wsum[32];
    __shared__ int wbase[32];
    int tid = threadIdx.x, lane = tid & 31, wid = tid >> 5;
    int v = (tid < n) ? bsum[tid] : 0;
    int x = v;
#pragma unroll
    for (int o = 1; o < 32; o <<= 1) {
        int t = __shfl_up_sync(0xffffffff, x, o);
        if (lane >= o) x += t;
    }
    if (lane == 31) wsum[wid] = x;
    __syncthreads();
    if (wid == 0) {
        int s = wsum[lane];
        int y = s;
#pragma unroll
        for (int o = 1; o < 32; o <<= 1) {
            int t = __shfl_up_sync(0xffffffff, y, o);
            if (lane >= o) y += t;
        }
        wbase[lane] = y - s;
    }
    __syncthreads();
    if (tid < n) bbase[tid] = wbase[wid] + x - v;
}

__global__ void offsets_kernel(const int* __restrict__ v_in, const int* __restrict__ bbase,
                               int* __restrict__ off, int n)
{
    __shared__ int wsum[32];
    __shared__ int wbase[32];
    int i = blockIdx.x * SCAN_BLK + threadIdx.x;
    int lane = threadIdx.x & 31, wid = threadIdx.x >> 5;
    int v = (i < n) ? v_in[i] : 0;
    int x = v;
#pragma unroll
    for (int o = 1; o < 32; o <<= 1) {
        int t = __shfl_up_sync(0xffffffff, x, o);
        if (lane >= o) x += t;
    }
    if (lane == 31) wsum[wid] = x;
    __syncthreads();
    if (wid == 0) {
        int s = wsum[lane];
        int y = s;
#pragma unroll
        for (int o = 1; o < 32; o <<= 1) {
            int t = __shfl_up_sync(0xffffffff, y, o);
            if (lane >= o) y += t;
        }
        wbase[lane] = y - s;
    }
    __syncthreads();
    if (i < n) off[i] = bbase[blockIdx.x] + wbase[wid] + x - v;
    if (i == n - 1) off[n] = bbase[blockIdx.x] + wbase[wid] + x;   // inclusive total
}

// fill CSR slots: eidx grouped by tgt, payload = (src<<3)|r
__global__ void fill_kernel(const int* __restrict__ edges, const int* __restrict__ off,
                            int* __restrict__ cursor, int* __restrict__ eidx)
{
    int i = blockIdx.x * 256 + threadIdx.x;
    if (i < NEDGE) {
        int r = i / EPR, e = i % EPR;
        int src = edges[r * 2 * EPR + e];
        int tgt = edges[r * 2 * EPR + EPR + e];
        int slot = off[tgt] + atomicAdd(&cursor[tgt], 1);
        eidx[slot] = (src << 3) | r;
    }
}

// compact active nodes per rel: rowlist[soff[i]] = node  (i = r*M + node)
__global__ void rowlist_kernel(const int* __restrict__ flag, const int* __restrict__ soff,
                               int* __restrict__ rowlist)
{
    int i = blockIdx.x * 256 + threadIdx.x;
    if (i < NBIN2 && flag[i])
        rowlist[soff[i]] = i % M_NODES;
}

// Wt[n][k] fp16
__global__ void convW_kernel(const float* __restrict__ Wrel, const float* __restrict__ Wself,
                             __half* __restrict__ Wt)
{
    int idx = blockIdx.x * 256 + threadIdx.x;
    if (idx < NMSG * HID) {
        int n = idx >> 8, k = idx & 255;
        float v = (n < 1536) ? Wrel[(((n >> 8) * 256) + k) * 256 + (n & 255)]
                             : Wself[k * 256 + (n & 255)];
        Wt[idx] = __float2half_rn(v);
    }
}

// ---------------- rel GEMM: compacted rows, grid (2, 782, 6) ----------------
__global__ __launch_bounds__(256, 2)
void gemm_rel(const __half* __restrict__ A, const __half* __restrict__ Wt,
              const int* __restrict__ soff, const int* __restrict__ rowlist,
              __half* __restrict__ msg)
{
    extern __shared__ unsigned char smraw[];
    const int rrel = blockIdx.z;
    const int base = __ldg(&soff[rrel * M_NODES]);
    const int cnt  = __ldg(&soff[(rrel + 1) * M_NODES]) - base;
    const int m0   = blockIdx.y * BM;
    if (m0 >= cnt) return;

    const int tid  = threadIdx.x;
    const int lane = tid & 31;
    const int wid  = tid >> 5;
    const int wm   = wid & 3;
    const int wn   = wid >> 2;
    const int n0   = blockIdx.x * BN;

    const int lrow = tid >> 3;
    const int lseg = tid & 7;

    int amrow[4];
#pragma unroll
    for (int p = 0; p < 4; p++) {
        int idx = m0 + lrow + p * 32;
        if (idx >= cnt) idx = cnt - 1;
        amrow[p] = __ldg(&rowlist[base + idx]);
    }

    float acc[2][8][4];
#pragma unroll
    for (int mi = 0; mi < 2; mi++)
#pragma unroll
        for (int ni = 0; ni < 8; ni++)
#pragma unroll
            for (int j = 0; j < 4; j++) acc[mi][ni][j] = 0.0f;

    unsigned aS[2], bS[2];
    aS[0] = su32(smraw);            bS[0] = su32(smraw + 16384);
    aS[1] = su32(smraw + 32768);    bS[1] = su32(smraw + 49152);

    auto issue = [&](int c, int st) {
        int koff = c * BK;
        unsigned char* As = smraw + st * 32768;
        unsigned char* Bs = smraw + st * 32768 + 16384;
#pragma unroll
        for (int p = 0; p < 4; p++) {
            int row = lrow + p * 32;
            unsigned so = swz((unsigned)(row * 128 + lseg * 16));
            cp16(As + so, A  + (size_t)amrow[p] * HID + koff + lseg * 8);
            cp16(Bs + so, Wt + (size_t)(rrel * 256 + n0 + row) * HID + koff + lseg * 8);
        }
        CP_COMMIT();
    };

    issue(0, 0);

    for (int c = 0; c < NCHUNK; ++c) {
        int st = c & 1;
        if (c + 1 < NCHUNK) { issue(c + 1, st ^ 1); CP_WAIT(1); }
        else                { CP_WAIT(0); }
        __syncthreads();

        unsigned ab = aS[st], bb = bS[st];
#pragma unroll
        for (int ks = 0; ks < 4; ++ks) {
            unsigned a[2][4], b[4][4];
#pragma unroll
            for (int mi = 0; mi < 2; mi++) {
                int row = wm * 32 + mi * 16 + (lane & 15);
                unsigned off = (unsigned)(row * 128 + ks * 32 + (lane >> 4) * 16);
                ldsm4(a[mi], ab + swz(off));
            }
#pragma unroll
            for (int nj = 0; nj < 4; nj++) {
                int q = lane >> 3, r2 = lane & 7;
                int nrow = wn * 64 + nj * 16 + (q >> 1) * 8 + r2;
                unsigned off = (unsigned)(nrow * 128 + ks * 32 + (q & 1) * 16);
                ldsm4(b[nj], bb + swz(off));
            }
#pragma unroll
            for (int mi = 0; mi < 2; mi++)
#pragma unroll
                for (int ni = 0; ni < 8; ni++)
                    mma16816(acc[mi][ni], a[mi], b[ni >> 1][(ni & 1) * 2], b[ni >> 1][(ni & 1) * 2 + 1]);
        }
        __syncthreads();
    }

    const int cb = rrel * 256 + n0 + wn * 64 + (lane & 3) * 2;
#pragma unroll
    for (int mi = 0; mi < 2; mi++) {
        int r0 = m0 + wm * 32 + mi * 16 + (lane >> 2);
        int r1 = r0 + 8;
        if (r0 < cnt) {
            int grow = __ldg(&rowlist[base + r0]);
            __half* dst = msg + (size_t)grow * NMSG + cb;
#pragma unroll
            for (int ni = 0; ni < 8; ni++)
                __stcs((__half2*)(dst + ni * 8), __floats2half2_rn(acc[mi][ni][0], acc[mi][ni][1]));
        }
        if (r1 < cnt) {
            int grow = __ldg(&rowlist[base + r1]);
            __half* dst = msg + (size_t)grow * NMSG + cb;
#pragma unroll
            for (int ni = 0; ni < 8; ni++)
                __stcs((__half2*)(dst + ni * 8), __floats2half2_rn(acc[mi][ni][2], acc[mi][ni][3]));
        }
    }
}

// ---------------- self GEMM: dense rows, cols 1536..1791, grid (2, 782) ----------------
__global__ __launch_bounds__(256, 2)
void gemm_self(const __half* __restrict__ A, const __half* __restrict__ Wt,
               __half* __restrict__ msg)
{
    extern __shared__ unsigned char smraw[];
    const int tid  = threadIdx.x;
    const int lane = tid & 31;
    const int wid  = tid >> 5;
    const int wm   = wid & 3;
    const int wn   = wid >> 2;
    const int m0   = blockIdx.y * BM;
    const int n0   = blockIdx.x * BN;

    const int lrow = tid >> 3;
    const int lseg = tid & 7;

    int amrow[4];
#pragma unroll
    for (int p = 0; p < 4; p++) {
        int m = m0 + lrow + p * 32;
        amrow[p] = m < M_NODES ? m : M_NODES - 1;
    }

    float acc[2][8][4];
#pragma unroll
    for (int mi = 0; mi < 2; mi++)
#pragma unroll
        for (int ni = 0; ni < 8; ni++)
#pragma unroll
            for (int j = 0; j < 4; j++) acc[mi][ni][j] = 0.0f;

    unsigned aS[2], bS[2];
    aS[0] = su32(smraw);            bS[0] = su32(smraw + 16384);
    aS[1] = su32(smraw + 32768);    bS[1] = su32(smraw + 49152);

    auto issue = [&](int c, int st) {
        int koff = c * BK;
        unsigned char* As = smraw + st * 32768;
        unsigned char* Bs = smraw + st * 32768 + 16384;
#pragma unroll
        for (int p = 0; p < 4; p++) {
            int row = lrow + p * 32;
            unsigned so = swz((unsigned)(row * 128 + lseg * 16));
            cp16(As + so, A  + (size_t)amrow[p] * HID + koff + lseg * 8);
            cp16(Bs + so, Wt + (size_t)(1536 + n0 + row) * HID + koff + lseg * 8);
        }
        CP_COMMIT();
    };

    issue(0, 0);

    for (int c = 0; c < NCHUNK; ++c) {
        int st = c & 1;
        if (c + 1 < NCHUNK) { issue(c + 1, st ^ 1); CP_WAIT(1); }
        else                { CP_WAIT(0); }
        __syncthreads();

        unsigned ab = aS[st], bb = bS[st];
#pragma unroll
        for (int ks = 0; ks < 4; ++ks) {
            unsigned a[2][4], b[4][4];
#pragma unroll
            for (int mi = 0; mi < 2; mi++) {
                int row = wm * 32 + mi * 16 + (lane & 15);
                unsigned off = (unsigned)(row * 128 + ks * 32 + (lane >> 4) * 16);
                ldsm4(a[mi], ab + swz(off));
            }
#pragma unroll
            for (int nj = 0; nj < 4; nj++) {
                int q = lane >> 3, r2 = lane & 7;
                int nrow = wn * 64 + nj * 16 + (q >> 1) * 8 + r2;
                unsigned off = (unsigned)(nrow * 128 + ks * 32 + (q & 1) * 16);
                ldsm4(b[nj], bb + swz(off));
            }
#pragma unroll
            for (int mi = 0; mi < 2; mi++)
#pragma unroll
                for (int ni = 0; ni < 8; ni++)
                    mma16816(acc[mi][ni], a[mi], b[ni >> 1][(ni & 1) * 2], b[ni >> 1][(ni & 1) * 2 + 1]);
        }
        __syncthreads();
    }

    const int cb = 1536 + n0 + wn * 64 + (lane & 3) * 2;
#pragma unroll
    for (int mi = 0; mi < 2; mi++) {
        int r0 = m0 + wm * 32 + mi * 16 + (lane >> 2);
        int r1 = r0 + 8;
        if (r0 < M_NODES) {
            __half* dst = msg + (size_t)r0 * NMSG + cb;
#pragma unroll
            for (int ni = 0; ni < 8; ni++)
                __stcs((__half2*)(dst + ni * 8), __floats2half2_rn(acc[mi][ni][0], acc[mi][ni][1]));
        }
        if (r1 < M_NODES) {
            __half* dst = msg + (size_t)r1 * NMSG + cb;
#pragma unroll
            for (int ni = 0; ni < 8; ni++)
                __stcs((__half2*)(dst + ni * 8), __floats2half2_rn(acc[mi][ni][2], acc[mi][ni][3]));
        }
    }
}

// ---------------- gather + combine: warp per node, x4 unroll, .cs streaming loads ----------------
__global__ __launch_bounds__(256)
void gather_kernel(const __half* __restrict__ msg, const int* __restrict__ off,
                   const int* __restrict__ eidx, const float* __restrict__ invd,
                   const float* __restrict__ bias, __half* __restrict__ hout)
{
    int node = blockIdx.x * 8 + (threadIdx.x >> 5);
    if (node >= M_NODES) return;
    const int lane = threadIdx.x & 31;

    int beg = __ldg(&off[node]);
    int end = __ldg(&off[node + 1]);

    float acc[8];
#pragma unroll
    for (int j = 0; j < 8; j++) acc[j] = 0.0f;

    auto accum = [&](uint4 u) {
        const __half2* h2 = (const __half2*)&u;
#pragma unroll
        for (int k = 0; k < 4; k++) {
            float2 f = __half22float2(h2[k]);
            acc[2 * k]     += f.x;
            acc[2 * k + 1] += f.y;
        }
    };
    auto rowptr = [&](int pk) {
        return (const uint4*)(msg + (size_t)(pk >> 3) * NMSG + (pk & 7) * HID + lane * 8);
    };

    int e = beg;
    for (; e + 3 < end; e += 4) {
        uint4 u0 = __ldcs(rowptr(__ldg(&eidx[e])));
        uint4 u1 = __ldcs(rowptr(__ldg(&eidx[e + 1])));
        uint4 u2 = __ldcs(rowptr(__ldg(&eidx[e + 2])));
        uint4 u3 = __ldcs(rowptr(__ldg(&eidx[e + 3])));
        accum(u0); accum(u1); accum(u2); accum(u3);
    }
    for (; e < end; ++e)
        accum(__ldcs(rowptr(__ldg(&eidx[e]))));

    float w = invd[node];
    uint4 s = __ldcs((const uint4*)(msg + (size_t)node * NMSG + 1536 + lane * 8));
    const __half2* s2 = (const __half2*)&s;
    float4 b0 = *(const float4*)(bias + lane * 8);
    float4 b1 = *(const float4*)(bias + lane * 8 + 4);
    float bb[8] = {b0.x, b0.y, b0.z, b0.w, b1.x, b1.y, b1.z, b1.w};

    uint4 outv;
    __half2* o2 = (__half2*)&outv;
#pragma unroll
    for (int k = 0; k < 4; k++) {
        float2 sf = __half22float2(s2[k]);
        float v0 = fmaxf(acc[2 * k]     * w + sf.x + bb[2 * k],     0.f);
        float v1 = fmaxf(acc[2 * k + 1] * w + sf.y + bb[2 * k + 1], 0.f);
        o2[k] = __floats2half2_rn(v0, v1);
    }
    *(uint4*)(hout + (size_t)node * HID + lane * 8) = outv;
}

// ---------------- pooling + MLP ----------------
__global__ void count_kernel(const int* __restrict__ bids, int* __restrict__ counts)
{
    int g = threadIdx.x;
    if (g >= NGRAPH) return;
    int lo = 0, hi = M_NODES;
    while (lo < hi) { int mid = (lo + hi) >> 1; if (bids[mid] < g) lo = mid + 1; else hi = mid; }
    int start = lo;
    lo = 0; hi = M_NODES;
    while (lo < hi) { int mid = (lo + hi) >> 1; if (bids[mid] <= g) lo = mid + 1; else hi = mid; }
    counts[g] = lo - start;
}

__global__ void pool_sum_kernel(const __half* __restrict__ h, const int* __restrict__ bids,
                                float* __restrict__ pooled)
{
    int c = threadIdx.x;
    int n_start = blockIdx.x * 256;
    int n_end = n_start + 256;
    if (n_end > M_NODES) n_end = M_NODES;
    if (n_start >= M_NODES) return;
    int cur = bids[n_start];
    float acc = 0.0f;
    for (int n = n_start; n < n_end; n++) {
        int g = bids[n];
        if (g != cur) { atomicAdd(&pooled[cur * HID + c], acc); acc = 0.0f; cur = g; }
        acc += __half2float(h[(size_t)n * HID + c]);
    }
    atomicAdd(&pooled[cur * HID + c], acc);
}

__global__ void mlp_kernel(const float* __restrict__ pooled, const int* __restrict__ counts,
                           const float* __restrict__ pW1, const float* __restrict__ pb1,
                           const float* __restrict__ pW2, const float* __restrict__ pb2,
                           float* __restrict__ out)
{
    __shared__ float p[HID];
    __shared__ float t[HID];
    int g = blockIdx.x, d = threadIdx.x;
    int cn = counts[g];
    float inv = 1.0f / (float)(cn > 1 ? cn : 1);
    p[d] = pooled[g * HID + d] * inv;
    __syncthreads();
    float a = pb1[d];
#pragma unroll 8
    for (int k = 0; k < HID; k++) a += p[k] * pW1[k * HID + d];
    t[d] = a > 0.f ? a : 0.f;
    __syncthreads();
    float o = pb2[d];
#pragma unroll 8
    for (int k = 0; k < HID; k++) o += t[k] * pW2[k * HID + d];
    out[g * HID + d] = o;
}

// ---------------------------------------------------------------
extern "C" void kernel_launch(void* const* d_in, const int* in_sizes, int n_in,
                              void* d_out, int out_size)
{
    const int*   x_type = (const int*)d_in[0];
    const int*   x_sub  = (const int*)d_in[1];
    const int*   edges  = (const int*)d_in[2];
    const int*   bids   = (const int*)d_in[3];
    const float* temb   = (const float*)d_in[5];
    const float* semb   = (const float*)d_in[6];
    const float* Wrel0  = (const float*)d_in[7];
    const float* Wself0 = (const float*)d_in[8];
    const float* b0     = (const float*)d_in[9];
    const float* Wrel1  = (const float*)d_in[10];
    const float* Wself1 = (const float*)d_in[11];
    const float* b1     = (const float*)d_in[12];
    const float* pW1    = (const float*)d_in[13];
    const float* pb1    = (const float*)d_in[14];
    const float* pW2    = (const float*)d_in[15];
    const float* pb2    = (const float*)d_in[16];
    float* out = (float*)d_out;

    void *phA, *phB, *pmsg, *pWt0, *pWt1, *pinv, *pdeg, *poff, *pbsum1, *pbbase1, *pcur, *peidx;
    void *pflag, *psoff, *pbsum2, *pbbase2, *prowlist, *ppooled, *pcnt;
    cudaGetSymbolAddress(&phA, g_hA16);
    cudaGetSymbolAddress(&phB, g_hB16);
    cudaGetSymbolAddress(&pmsg, g_msg);
    cudaGetSymbolAddress(&pWt0, g_Wt0);
    cudaGetSymbolAddress(&pWt1, g_Wt1);
    cudaGetSymbolAddress(&pinv, g_invdeg);
    cudaGetSymbolAddress(&pdeg, g_deg);
    cudaGetSymbolAddress(&poff, g_off);
    cudaGetSymbolAddress(&pbsum1, g_bsum1);
    cudaGetSymbolAddress(&pbbase1, g_bbase1);
    cudaGetSymbolAddress(&pcur, g_cursor);
    cudaGetSymbolAddress(&peidx, g_eidx);
    cudaGetSymbolAddress(&pflag, g_flag);
    cudaGetSymbolAddress(&psoff, g_soff);
    cudaGetSymbolAddress(&pbsum2, g_bsum2);
    cudaGetSymbolAddress(&pbbase2, g_bbase2);
    cudaGetSymbolAddress(&prowlist, g_rowlist);
    cudaGetSymbolAddress(&ppooled, g_pooled);
    cudaGetSymbolAddress(&pcnt, g_counts);

    cudaFuncSetAttribute(gemm_rel, cudaFuncAttributeMaxDynamicSharedMemorySize, GSMEM);
    cudaFuncSetAttribute(gemm_self, cudaFuncAttributeMaxDynamicSharedMemorySize, GSMEM);

    // ---- fork a side stream for graph prework (depends only on `edges`) ----
    cudaStream_t side;
    cudaEvent_t evFork, evJoin;
    cudaStreamCreateWithFlags(&side, cudaStreamNonBlocking);
    cudaEventCreateWithFlags(&evFork, cudaEventDisableTiming);
    cudaEventCreateWithFlags(&evJoin, cudaEventDisableTiming);

    cudaEventRecord(evFork, 0);
    cudaStreamWaitEvent(side, evFork, 0);

    // side stream: CSR-by-tgt + (rel,src) rowlist + invdeg
    cudaMemsetAsync(pdeg, 0, M_NODES * sizeof(int), side);
    cudaMemsetAsync(pcur, 0, M_NODES * sizeof(int), side);
    cudaMemsetAsync(pflag, 0, NBIN2 * sizeof(int), side);
    degflag_kernel<<<(NEDGE + 255) / 256, 256, 0, side>>>(edges, (int*)pdeg, (int*)pflag);
    invdeg_kernel<<<(M_NODES + 255) / 256, 256, 0, side>>>((const int*)pdeg, (float*)pinv);
    blocksum_kernel<<<NSCAN1, SCAN_BLK, 0, side>>>((const int*)pdeg, (int*)pbsum1, M_NODES);
    bscan_kernel<<<1, SCAN_BLK, 0, side>>>((const int*)pbsum1, (int*)pbbase1, NSCAN1);
    offsets_kernel<<<NSCAN1, SCAN_BLK, 0, side>>>((const int*)pdeg, (const int*)pbbase1, (int*)poff, M_NODES);
    fill_kernel<<<(NEDGE + 255) / 256, 256, 0, side>>>(edges, (const int*)poff, (int*)pcur, (int*)peidx);
    blocksum_kernel<<<NSCAN2, SCAN_BLK, 0, side>>>((const int*)pflag, (int*)pbsum2, NBIN2);
    bscan_kernel<<<1, SCAN_BLK, 0, side>>>((const int*)pbsum2, (int*)pbbase2, NSCAN2);
    offsets_kernel<<<NSCAN2, SCAN_BLK, 0, side>>>((const int*)pflag, (const int*)pbbase2, (int*)psoff, NBIN2);
    rowlist_kernel<<<(NBIN2 + 255) / 256, 256, 0, side>>>((const int*)pflag, (const int*)psoff, (int*)prowlist);
    cudaEventRecord(evJoin, side);

    // main stream: structure-independent work runs concurrently with prework
    cudaMemsetAsync(ppooled, 0, NGRAPH * HID * sizeof(float));
    embed_kernel<<<(M_NODES * HID + 255) / 256, 256>>>(x_type, x_sub, temb, semb, (__half*)phA);
    convW_kernel<<<(NMSG * HID + 255) / 256, 256>>>(Wrel0, Wself0, (__half*)pWt0);
    convW_kernel<<<(NMSG * HID + 255) / 256, 256>>>(Wrel1, Wself1, (__half*)pWt1);

    dim3 rgrid(2, (M_NODES + BM - 1) / BM, NREL);   // (2, 782, 6), early-exit above cnt
    dim3 sgrid(2, (M_NODES + BM - 1) / BM);         // (2, 782)
    int gblocks = (M_NODES + 7) / 8;

    // ---- layer 0: hA -> hB ----
    gemm_self<<<sgrid, 256, GSMEM>>>((const __half*)phA, (const __half*)pWt0, (__half*)pmsg);
    cudaStreamWaitEvent(0, evJoin, 0);   // join: rel-GEMM and gather need rowlist/CSR
    gemm_rel<<<rgrid, 256, GSMEM>>>((const __half*)phA, (const __half*)pWt0,
                                    (const int*)psoff, (const int*)prowlist, (__half*)pmsg);
    gather_kernel<<<gblocks, 256>>>((const __half*)pmsg, (const int*)poff, (const int*)peidx,
                                    (const float*)pinv, b0, (__half*)phB);

    // ---- layer 1: hB -> hA ----
    gemm_rel<<<rgrid, 256, GSMEM>>>((const __half*)phB, (const __half*)pWt1,
                                    (const int*)psoff, (const int*)prowlist, (__half*)pmsg);
    gemm_self<<<sgrid, 256, GSMEM>>>((const __half*)phB, (const __half*)pWt1, (__half*)pmsg);
    gather_kernel<<<gblocks, 256>>>((const __half*)pmsg, (const int*)poff, (const int*)peidx,
                                    (const float*)pinv, b1, (__half*)phA);

    // ---- pool + MLP ----
    count_kernel<<<1, 128>>>(bids, (int*)pcnt);
    pool_sum_kernel<<<(M_NODES + 255) / 256, 256>>>((const __half*)phA, bids, (float*)ppooled);
    mlp_kernel<<<NGRAPH, 256>>>((const float*)ppooled, (const int*)pcnt, pW1, pb1, pW2, pb2, out);

    // side stream was joined back into the main stream; safe to release handles
    cudaEventDestroy(evFork);
    cudaEventDestroy(evJoin);
    cudaStreamDestroy(side);
}